// round 2
// baseline (speedup 1.0000x reference)
#include <cuda_runtime.h>
#include <math.h>

#define NTHREADS 512
#define NNODES   256
#define ROWSTR   129   // 128 + 1 pad: conflict-free per-row and per-column access

// shared memory carve (floats)
#define X2_SZ   (NNODES * ROWSTR)        // 33024  node activations [256][129]
#define W_SZ    (16384 + 3 * 128)        // 16768  current-stage weights + b,g,be
#define RED_SZ  1536                     // top-2 partials (8 chunks) / colmax partials
#define FIN_SZ  192                      // final m1,m2,i1 per channel
#define SMEM_FLOATS (X2_SZ + W_SZ + RED_SZ + FIN_SZ)
#define SMEM_BYTES  (SMEM_FLOATS * 4)

// pair-wise LayerNorm+ReLU: each thread holds C/2 channels of a C-wide row;
// partner thread is lane^1 in the same warp.
template<int CHALF>
__device__ __forceinline__ void ln_relu_pair(float* h, const float* g, const float* be,
                                             float invC) {
    float s = 0.f;
#pragma unroll
    for (int i = 0; i < CHALF; i++) s += h[i];
    s += __shfl_xor_sync(0xffffffffu, s, 1);
    float mu = s * invC;
    float v = 0.f;
#pragma unroll
    for (int i = 0; i < CHALF; i++) { float d = h[i] - mu; v += d * d; }
    v += __shfl_xor_sync(0xffffffffu, v, 1);
    float rs = rsqrtf(v * invC + 1e-5f);
#pragma unroll
    for (int i = 0; i < CHALF; i++) {
        float t = (h[i] - mu) * rs * g[i] + be[i];
        h[i] = fmaxf(t, 0.0f);
    }
}

__global__ __launch_bounds__(NTHREADS, 1)
void localgraph_fused_kernel(
    const float* __restrict__ inp,
    const float* __restrict__ W0, const float* __restrict__ b0, const float* __restrict__ g0, const float* __restrict__ be0,
    const float* __restrict__ W1, const float* __restrict__ b1, const float* __restrict__ g1, const float* __restrict__ be1,
    const float* __restrict__ W2, const float* __restrict__ b2, const float* __restrict__ g2, const float* __restrict__ be2,
    const float* __restrict__ W3, const float* __restrict__ b3, const float* __restrict__ g3, const float* __restrict__ be3,
    float* __restrict__ out)
{
    extern __shared__ float smem[];
    float* sx   = smem;                 // [256][129]
    float* sw   = smem + X2_SZ;         // weights region (reused per stage)
    float* sred = sw + W_SZ;            // reduction scratch
    float* sfin = sred + RED_SZ;        // final top-2 per channel

    const int tid  = threadIdx.x;
    const int bm   = blockIdx.x;        // (b*M + m)
    const int n    = tid >> 1;          // node index (2 threads per node)
    const int half = tid & 1;           // which half of the output channels
    float* row = sx + n * ROWSTR;

    // ---- load input row (pair reads same 32B; warp covers 512B contiguous) ----
    float x[8];
    {
        const float4* p = reinterpret_cast<const float4*>(inp + ((size_t)bm * NNODES + n) * 8);
        float4 a = p[0], b = p[1];
        x[0]=a.x; x[1]=a.y; x[2]=a.z; x[3]=a.w;
        x[4]=b.x; x[5]=b.y; x[6]=b.z; x[7]=b.w;
    }

    // ---- stage-1 weights: W0(512) b0 g0 be0 | W1(4096) b1 g1 be1 ----
    for (int i = tid; i < 512;  i += NTHREADS) sw[i]        = W0[i];
    if (tid < 64) { sw[512+tid]=b0[tid]; sw[576+tid]=g0[tid]; sw[640+tid]=be0[tid]; }
    for (int i = tid; i < 4096; i += NTHREADS) sw[704+i]    = W1[i];
    if (tid >= 64 && tid < 128) {
        int i = tid - 64;
        sw[4800+i]=b1[i]; sw[4864+i]=g1[i]; sw[4928+i]=be1[i];
    }
    __syncthreads();

    // ---- mlp0: 8 -> 64, LN, ReLU  (this thread: 32 outputs at ob32) ----
    const int ob32 = half * 32;
    float h[32];
#pragma unroll
    for (int o = 0; o < 32; o++) h[o] = sw[512 + ob32 + o];
#pragma unroll
    for (int k = 0; k < 8; k++) {
        float xk = x[k];
        const float4* w4 = reinterpret_cast<const float4*>(&sw[k * 64 + ob32]);
#pragma unroll
        for (int o = 0; o < 8; o++) {
            float4 w = w4[o];
            h[4*o+0] += xk * w.x; h[4*o+1] += xk * w.y;
            h[4*o+2] += xk * w.z; h[4*o+3] += xk * w.w;
        }
    }
    ln_relu_pair<32>(h, sw + 576 + ob32, sw + 640 + ob32, 1.0f/64.0f);
#pragma unroll
    for (int o = 0; o < 32; o++) row[ob32 + o] = h[o];
    __syncwarp();

    // ---- mlp1: 64 -> 64, LN, ReLU ----
    float e2[32];
#pragma unroll
    for (int o = 0; o < 32; o++) e2[o] = sw[4800 + ob32 + o];
    for (int k = 0; k < 64; k++) {
        float xk = row[k];
        const float4* w4 = reinterpret_cast<const float4*>(&sw[704 + k * 64 + ob32]);
#pragma unroll
        for (int o = 0; o < 8; o++) {
            float4 w = w4[o];
            e2[4*o+0] += xk * w.x; e2[4*o+1] += xk * w.y;
            e2[4*o+2] += xk * w.z; e2[4*o+3] += xk * w.w;
        }
    }
    ln_relu_pair<32>(e2, sw + 4864 + ob32, sw + 4928 + ob32, 1.0f/64.0f);
    __syncwarp();                        // partner done reading h from row
#pragma unroll
    for (int o = 0; o < 32; o++) row[ob32 + o] = e2[o];
    __syncthreads();

    // ---- exclude-self max over 256 nodes, per channel (top-2 + argmax) ----
    {
        // 8 chunks of 32 nodes x 64 channels; thread = (chunk, channel)
        const int ch = tid & 63, chunk = tid >> 6;
        float m1 = -INFINITY, m2 = -INFINITY; int i1 = -1;
        const int jb = chunk * 32;
        for (int j = 0; j < 32; j++) {
            float v = sx[(jb + j) * ROWSTR + ch];
            if (v > m1)      { m2 = m1; m1 = v; i1 = jb + j; }
            else if (v > m2) { m2 = v; }
        }
        sred[chunk * 64 + ch]       = m1;
        sred[512 + chunk * 64 + ch] = m2;
        reinterpret_cast<int*>(sred)[1024 + chunk * 64 + ch] = i1;
    }
    __syncthreads();
    if (tid < 64) {
        float m1 = sred[tid], m2 = sred[512 + tid];
        int   i1 = reinterpret_cast<int*>(sred)[1024 + tid];
#pragma unroll
        for (int c = 1; c < 8; c++) {
            float a1 = sred[c * 64 + tid], a2 = sred[512 + c * 64 + tid];
            int   ai = reinterpret_cast<int*>(sred)[1024 + c * 64 + tid];
            if (a1 > m1) { m2 = fmaxf(m1, a2); m1 = a1; i1 = ai; }
            else         { m2 = fmaxf(m2, a1); }
        }
        sfin[tid] = m1; sfin[64 + tid] = m2;
        reinterpret_cast<int*>(sfin)[128 + tid] = i1;
    }
    __syncthreads();

    // concat: row[64+d] = max(excl_n(d), e2[n][d] - 10000); 32 channels per thread
#pragma unroll
    for (int j = 0; j < 32; j++) {
        int d = ob32 + j;
        float v  = row[d];
        float m1 = sfin[d], m2 = sfin[64 + d];
        int   i1 = reinterpret_cast<int*>(sfin)[128 + d];
        float excl = (i1 == n) ? m2 : m1;
        row[64 + d] = fmaxf(excl, v - 10000.0f);
    }

    // ---- stage-2 weights: W2(16384) b2 g2 be2 (overwrites stage-1 region) ----
    for (int i = tid; i < 16384; i += NTHREADS) sw[i] = W2[i];
    if (tid < 128) { sw[16384+tid]=b2[tid]; sw[16512+tid]=g2[tid]; sw[16640+tid]=be2[tid]; }
    __syncthreads();

    // ---- mlp2: 128 -> 128, LN, ReLU (this thread: 64 outputs at ob64) ----
    const int ob64 = half * 64;
    float acc[64];
#pragma unroll
    for (int o = 0; o < 64; o++) acc[o] = sw[16384 + ob64 + o];
    for (int k = 0; k < 128; k++) {
        float xk = row[k];
        const float4* w4 = reinterpret_cast<const float4*>(&sw[k * 128 + ob64]);
#pragma unroll
        for (int o = 0; o < 16; o++) {
            float4 w = w4[o];
            acc[4*o+0] += xk * w.x; acc[4*o+1] += xk * w.y;
            acc[4*o+2] += xk * w.z; acc[4*o+3] += xk * w.w;
        }
    }
    ln_relu_pair<64>(acc, sw + 16512 + ob64, sw + 16640 + ob64, 1.0f/128.0f);
    __syncwarp();                        // partner done reading row
#pragma unroll
    for (int o = 0; o < 64; o++) row[ob64 + o] = acc[o];

    // ---- stage-3 weights: W3 b3 g3 be3 ----
    __syncthreads();                     // everyone done reading W2
    for (int i = tid; i < 16384; i += NTHREADS) sw[i] = W3[i];
    if (tid < 128) { sw[16384+tid]=b3[tid]; sw[16512+tid]=g3[tid]; sw[16640+tid]=be3[tid]; }
    __syncthreads();

    // ---- mlp3: 128 -> 128, LN, ReLU ----
#pragma unroll
    for (int o = 0; o < 64; o++) acc[o] = sw[16384 + ob64 + o];
    for (int k = 0; k < 128; k++) {
        float xk = row[k];
        const float4* w4 = reinterpret_cast<const float4*>(&sw[k * 128 + ob64]);
#pragma unroll
        for (int o = 0; o < 16; o++) {
            float4 w = w4[o];
            acc[4*o+0] += xk * w.x; acc[4*o+1] += xk * w.y;
            acc[4*o+2] += xk * w.z; acc[4*o+3] += xk * w.w;
        }
    }
    ln_relu_pair<64>(acc, sw + 16512 + ob64, sw + 16640 + ob64, 1.0f/128.0f);
    __syncwarp();
#pragma unroll
    for (int o = 0; o < 64; o++) row[ob64 + o] = acc[o];
    __syncthreads();

    // ---- final: out[:,:,d] = out[:,:,128+d] = max_n e4[n][d]
    // (max over n of the exclude-self neighborhood equals the plain column max:
    //  for any n != argmax, excl = m1, and x - 10000 < m1 always)
    {
        const int d = tid & 127, chunk = tid >> 7;   // 4 chunks x 64 nodes
        float m = -INFINITY;
        const int jb = chunk * 64;
        for (int j = 0; j < 64; j++) m = fmaxf(m, sx[(jb + j) * ROWSTR + d]);
        sred[chunk * 128 + d] = m;
    }
    __syncthreads();
    if (tid < 128) {
        float m = fmaxf(fmaxf(sred[tid], sred[128 + tid]),
                        fmaxf(sred[256 + tid], sred[384 + tid]));
        out[(size_t)bm * 256 + tid]       = m;
        out[(size_t)bm * 256 + 128 + tid] = m;
    }
}

extern "C" void kernel_launch(void* const* d_in, const int* in_sizes, int n_in,
                              void* d_out, int out_size)
{
    // Identify input_states by its unique element count; take the 16 weight
    // tensors in their relative order (robust to metadata ordering).
    const int INPUT_ELEMS = 8 * 128 * 256 * 8;   // 2,097,152
    const float* inp = nullptr;
    const float* w[16];
    int wi = 0;
    for (int i = 0; i < n_in; i++) {
        if (in_sizes[i] == INPUT_ELEMS) inp = (const float*)d_in[i];
        else if (wi < 16)               w[wi++] = (const float*)d_in[i];
    }

    cudaFuncSetAttribute(localgraph_fused_kernel,
                         cudaFuncAttributeMaxDynamicSharedMemorySize, SMEM_BYTES);

    localgraph_fused_kernel<<<8 * 128, NTHREADS, SMEM_BYTES>>>(
        inp,
        w[0],  w[1],  w[2],  w[3],
        w[4],  w[5],  w[6],  w[7],
        w[8],  w[9],  w[10], w[11],
        w[12], w[13], w[14], w[15],
        (float*)d_out);
}

// round 3
// speedup vs baseline: 1.6641x; 1.6641x over previous
#include <cuda_runtime.h>
#include <math.h>

#define NTHREADS 512
#define NNODES   256
#define ROWSTR   129   // 128 + 1 pad: conflict-free row/column access

// shared memory carve (floats)
#define X2_SZ   (NNODES * ROWSTR)        // 33024  node activations [256][129]
#define W_SZ    (16384 + 3 * 128)        // 16768  current-stage weights + b,g,be
#define RED_SZ  1536                     // top-2 partials (8 chunks) / colmax partials
#define FIN_SZ  192                      // final m1,m2,i1 per channel
#define SMEM_FLOATS (X2_SZ + W_SZ + RED_SZ + FIN_SZ)
#define SMEM_BYTES  (SMEM_FLOATS * 4)

// Channel ownership (interleaved to keep the pair's LDS.128 bank-disjoint):
//   thread with `half` owns channels d = 8*o + 4*half + j,  j in [0,4)
//   -> pair addresses differ by 16B (adjacent banks), NOT 256B (same bank).

__global__ __launch_bounds__(NTHREADS, 1)
void localgraph_fused_kernel(
    const float* __restrict__ inp,
    const float* __restrict__ W0, const float* __restrict__ b0, const float* __restrict__ g0, const float* __restrict__ be0,
    const float* __restrict__ W1, const float* __restrict__ b1, const float* __restrict__ g1, const float* __restrict__ be1,
    const float* __restrict__ W2, const float* __restrict__ b2, const float* __restrict__ g2, const float* __restrict__ be2,
    const float* __restrict__ W3, const float* __restrict__ b3, const float* __restrict__ g3, const float* __restrict__ be3,
    float* __restrict__ out)
{
    extern __shared__ float smem[];
    float* sx   = smem;                 // [256][129]
    float* sw   = smem + X2_SZ;         // weights region (reused per stage)
    float* sred = sw + W_SZ;            // reduction scratch
    float* sfin = sred + RED_SZ;        // final top-2 per channel

    const int tid  = threadIdx.x;
    const int bm   = blockIdx.x;        // (b*M + m)
    const int n    = tid >> 1;          // node index (2 threads per node)
    const int half = tid & 1;
    const int co   = half * 4;          // channel sub-offset within each 8-group
    float* row = sx + n * ROWSTR;

    // ---- load input row ----
    float x[8];
    {
        const float4* p = reinterpret_cast<const float4*>(inp + ((size_t)bm * NNODES + n) * 8);
        float4 a = p[0], b = p[1];
        x[0]=a.x; x[1]=a.y; x[2]=a.z; x[3]=a.w;
        x[4]=b.x; x[5]=b.y; x[6]=b.z; x[7]=b.w;
    }

    // ---- stage-1 weights: W0(512) b0 g0 be0 | W1(4096) b1 g1 be1 ----
    for (int i = tid; i < 512;  i += NTHREADS) sw[i]     = W0[i];
    if (tid < 64) { sw[512+tid]=b0[tid]; sw[576+tid]=g0[tid]; sw[640+tid]=be0[tid]; }
    for (int i = tid; i < 4096; i += NTHREADS) sw[704+i] = W1[i];
    if (tid >= 64 && tid < 128) {
        int i = tid - 64;
        sw[4800+i]=b1[i]; sw[4864+i]=g1[i]; sw[4928+i]=be1[i];
    }
    __syncthreads();

    // ---- mlp0: 8 -> 64, LN, ReLU  (thread: 32 channels, interleaved) ----
    float h[32];
#pragma unroll
    for (int o = 0; o < 8; o++) {
        float4 b4 = *reinterpret_cast<const float4*>(&sw[512 + 8*o + co]);
        h[4*o+0]=b4.x; h[4*o+1]=b4.y; h[4*o+2]=b4.z; h[4*o+3]=b4.w;
    }
#pragma unroll
    for (int k = 0; k < 8; k++) {
        float xk = x[k];
#pragma unroll
        for (int o = 0; o < 8; o++) {
            float4 w = *reinterpret_cast<const float4*>(&sw[k*64 + 8*o + co]);
            h[4*o+0] += xk * w.x; h[4*o+1] += xk * w.y;
            h[4*o+2] += xk * w.z; h[4*o+3] += xk * w.w;
        }
    }
    {   // LN(64) across the pair + ReLU
        float s = 0.f;
#pragma unroll
        for (int i = 0; i < 32; i++) s += h[i];
        s += __shfl_xor_sync(0xffffffffu, s, 1);
        float mu = s * (1.0f/64.0f), v = 0.f;
#pragma unroll
        for (int i = 0; i < 32; i++) { float d = h[i] - mu; v += d * d; }
        v += __shfl_xor_sync(0xffffffffu, v, 1);
        float rs = rsqrtf(v * (1.0f/64.0f) + 1e-5f);
#pragma unroll
        for (int o = 0; o < 8; o++) {
            float4 g4  = *reinterpret_cast<const float4*>(&sw[576 + 8*o + co]);
            float4 be4 = *reinterpret_cast<const float4*>(&sw[640 + 8*o + co]);
            h[4*o+0] = fmaxf((h[4*o+0]-mu)*rs*g4.x + be4.x, 0.f);
            h[4*o+1] = fmaxf((h[4*o+1]-mu)*rs*g4.y + be4.y, 0.f);
            h[4*o+2] = fmaxf((h[4*o+2]-mu)*rs*g4.z + be4.z, 0.f);
            h[4*o+3] = fmaxf((h[4*o+3]-mu)*rs*g4.w + be4.w, 0.f);
        }
    }
#pragma unroll
    for (int o = 0; o < 8; o++) {
        row[8*o+co+0]=h[4*o+0]; row[8*o+co+1]=h[4*o+1];
        row[8*o+co+2]=h[4*o+2]; row[8*o+co+3]=h[4*o+3];
    }
    __syncwarp();

    // ---- mlp1: 64 -> 64, LN, ReLU ----
    float e2[32];
#pragma unroll
    for (int o = 0; o < 8; o++) {
        float4 b4 = *reinterpret_cast<const float4*>(&sw[4800 + 8*o + co]);
        e2[4*o+0]=b4.x; e2[4*o+1]=b4.y; e2[4*o+2]=b4.z; e2[4*o+3]=b4.w;
    }
    for (int k = 0; k < 64; k++) {
        float xk = row[k];
#pragma unroll
        for (int o = 0; o < 8; o++) {
            float4 w = *reinterpret_cast<const float4*>(&sw[704 + k*64 + 8*o + co]);
            e2[4*o+0] += xk * w.x; e2[4*o+1] += xk * w.y;
            e2[4*o+2] += xk * w.z; e2[4*o+3] += xk * w.w;
        }
    }
    {
        float s = 0.f;
#pragma unroll
        for (int i = 0; i < 32; i++) s += e2[i];
        s += __shfl_xor_sync(0xffffffffu, s, 1);
        float mu = s * (1.0f/64.0f), v = 0.f;
#pragma unroll
        for (int i = 0; i < 32; i++) { float d = e2[i] - mu; v += d * d; }
        v += __shfl_xor_sync(0xffffffffu, v, 1);
        float rs = rsqrtf(v * (1.0f/64.0f) + 1e-5f);
#pragma unroll
        for (int o = 0; o < 8; o++) {
            float4 g4  = *reinterpret_cast<const float4*>(&sw[4864 + 8*o + co]);
            float4 be4 = *reinterpret_cast<const float4*>(&sw[4928 + 8*o + co]);
            e2[4*o+0] = fmaxf((e2[4*o+0]-mu)*rs*g4.x + be4.x, 0.f);
            e2[4*o+1] = fmaxf((e2[4*o+1]-mu)*rs*g4.y + be4.y, 0.f);
            e2[4*o+2] = fmaxf((e2[4*o+2]-mu)*rs*g4.z + be4.z, 0.f);
            e2[4*o+3] = fmaxf((e2[4*o+3]-mu)*rs*g4.w + be4.w, 0.f);
        }
    }
    __syncwarp();                        // partner done reading h from row
#pragma unroll
    for (int o = 0; o < 8; o++) {
        row[8*o+co+0]=e2[4*o+0]; row[8*o+co+1]=e2[4*o+1];
        row[8*o+co+2]=e2[4*o+2]; row[8*o+co+3]=e2[4*o+3];
    }
    __syncthreads();

    // ---- exclude-self max over 256 nodes, per channel (top-2 + argmax) ----
    {
        const int ch = tid & 63, chunk = tid >> 6;   // 8 chunks x 32 nodes
        float m1 = -INFINITY, m2 = -INFINITY; int i1 = -1;
        const int jb = chunk * 32;
        for (int j = 0; j < 32; j++) {
            float v = sx[(jb + j) * ROWSTR + ch];
            if (v > m1)      { m2 = m1; m1 = v; i1 = jb + j; }
            else if (v > m2) { m2 = v; }
        }
        sred[chunk * 64 + ch]       = m1;
        sred[512 + chunk * 64 + ch] = m2;
        reinterpret_cast<int*>(sred)[1024 + chunk * 64 + ch] = i1;
    }
    __syncthreads();
    if (tid < 64) {
        float m1 = sred[tid], m2 = sred[512 + tid];
        int   i1 = reinterpret_cast<int*>(sred)[1024 + tid];
#pragma unroll
        for (int c = 1; c < 8; c++) {
            float a1 = sred[c * 64 + tid], a2 = sred[512 + c * 64 + tid];
            int   ai = reinterpret_cast<int*>(sred)[1024 + c * 64 + tid];
            if (a1 > m1) { m2 = fmaxf(m1, a2); m1 = a1; i1 = ai; }
            else         { m2 = fmaxf(m2, a1); }
        }
        sfin[tid] = m1; sfin[64 + tid] = m2;
        reinterpret_cast<int*>(sfin)[128 + tid] = i1;
    }
    __syncthreads();

    // concat: row[64+d] = max(excl_n(d), e2[n][d] - 10000); 32 channels/thread
    {
        const int db = half * 32;
#pragma unroll
        for (int j = 0; j < 32; j++) {
            int d = db + j;
            float v  = row[d];
            float m1 = sfin[d], m2 = sfin[64 + d];
            int   i1 = reinterpret_cast<int*>(sfin)[128 + d];
            float excl = (i1 == n) ? m2 : m1;
            row[64 + d] = fmaxf(excl, v - 10000.0f);
        }
    }

    // ---- stage-2 weights: W2(16384) b2 g2 be2 ----
    for (int i = tid; i < 16384; i += NTHREADS) sw[i] = W2[i];
    if (tid < 128) { sw[16384+tid]=b2[tid]; sw[16512+tid]=g2[tid]; sw[16640+tid]=be2[tid]; }
    __syncthreads();

    // ---- mlp2: 128 -> 128, LN, ReLU (thread: 64 channels, interleaved) ----
    float acc[64];
#pragma unroll
    for (int o = 0; o < 16; o++) {
        float4 b4 = *reinterpret_cast<const float4*>(&sw[16384 + 8*o + co]);
        acc[4*o+0]=b4.x; acc[4*o+1]=b4.y; acc[4*o+2]=b4.z; acc[4*o+3]=b4.w;
    }
    for (int k = 0; k < 128; k++) {
        float xk = row[k];
#pragma unroll
        for (int o = 0; o < 16; o++) {
            float4 w = *reinterpret_cast<const float4*>(&sw[k*128 + 8*o + co]);
            acc[4*o+0] += xk * w.x; acc[4*o+1] += xk * w.y;
            acc[4*o+2] += xk * w.z; acc[4*o+3] += xk * w.w;
        }
    }
    {
        float s = 0.f;
#pragma unroll
        for (int i = 0; i < 64; i++) s += acc[i];
        s += __shfl_xor_sync(0xffffffffu, s, 1);
        float mu = s * (1.0f/128.0f), v = 0.f;
#pragma unroll
        for (int i = 0; i < 64; i++) { float d = acc[i] - mu; v += d * d; }
        v += __shfl_xor_sync(0xffffffffu, v, 1);
        float rs = rsqrtf(v * (1.0f/128.0f) + 1e-5f);
#pragma unroll
        for (int o = 0; o < 16; o++) {
            float4 g4  = *reinterpret_cast<const float4*>(&sw[16512 + 8*o + co]);
            float4 be4 = *reinterpret_cast<const float4*>(&sw[16640 + 8*o + co]);
            acc[4*o+0] = fmaxf((acc[4*o+0]-mu)*rs*g4.x + be4.x, 0.f);
            acc[4*o+1] = fmaxf((acc[4*o+1]-mu)*rs*g4.y + be4.y, 0.f);
            acc[4*o+2] = fmaxf((acc[4*o+2]-mu)*rs*g4.z + be4.z, 0.f);
            acc[4*o+3] = fmaxf((acc[4*o+3]-mu)*rs*g4.w + be4.w, 0.f);
        }
    }
    __syncwarp();                        // partner done reading row
#pragma unroll
    for (int o = 0; o < 16; o++) {
        row[8*o+co+0]=acc[4*o+0]; row[8*o+co+1]=acc[4*o+1];
        row[8*o+co+2]=acc[4*o+2]; row[8*o+co+3]=acc[4*o+3];
    }

    // ---- stage-3 weights: W3 b3 g3 be3 ----
    __syncthreads();                     // everyone done reading W2
    for (int i = tid; i < 16384; i += NTHREADS) sw[i] = W3[i];
    if (tid < 128) { sw[16384+tid]=b3[tid]; sw[16512+tid]=g3[tid]; sw[16640+tid]=be3[tid]; }
    __syncthreads();

    // ---- mlp3: 128 -> 128, LN, ReLU ----
#pragma unroll
    for (int o = 0; o < 16; o++) {
        float4 b4 = *reinterpret_cast<const float4*>(&sw[16384 + 8*o + co]);
        acc[4*o+0]=b4.x; acc[4*o+1]=b4.y; acc[4*o+2]=b4.z; acc[4*o+3]=b4.w;
    }
    for (int k = 0; k < 128; k++) {
        float xk = row[k];
#pragma unroll
        for (int o = 0; o < 16; o++) {
            float4 w = *reinterpret_cast<const float4*>(&sw[k*128 + 8*o + co]);
            acc[4*o+0] += xk * w.x; acc[4*o+1] += xk * w.y;
            acc[4*o+2] += xk * w.z; acc[4*o+3] += xk * w.w;
        }
    }
    {
        float s = 0.f;
#pragma unroll
        for (int i = 0; i < 64; i++) s += acc[i];
        s += __shfl_xor_sync(0xffffffffu, s, 1);
        float mu = s * (1.0f/128.0f), v = 0.f;
#pragma unroll
        for (int i = 0; i < 64; i++) { float d = acc[i] - mu; v += d * d; }
        v += __shfl_xor_sync(0xffffffffu, v, 1);
        float rs = rsqrtf(v * (1.0f/128.0f) + 1e-5f);
#pragma unroll
        for (int o = 0; o < 16; o++) {
            float4 g4  = *reinterpret_cast<const float4*>(&sw[16512 + 8*o + co]);
            float4 be4 = *reinterpret_cast<const float4*>(&sw[16640 + 8*o + co]);
            acc[4*o+0] = fmaxf((acc[4*o+0]-mu)*rs*g4.x + be4.x, 0.f);
            acc[4*o+1] = fmaxf((acc[4*o+1]-mu)*rs*g4.y + be4.y, 0.f);
            acc[4*o+2] = fmaxf((acc[4*o+2]-mu)*rs*g4.z + be4.z, 0.f);
            acc[4*o+3] = fmaxf((acc[4*o+3]-mu)*rs*g4.w + be4.w, 0.f);
        }
    }
    __syncwarp();
#pragma unroll
    for (int o = 0; o < 16; o++) {
        row[8*o+co+0]=acc[4*o+0]; row[8*o+co+1]=acc[4*o+1];
        row[8*o+co+2]=acc[4*o+2]; row[8*o+co+3]=acc[4*o+3];
    }
    __syncthreads();

    // ---- final: out[:,:,d] = out[:,:,128+d] = max_n e4[n][d] ----
    {
        const int d = tid & 127, chunk = tid >> 7;   // 4 chunks x 64 nodes
        float m = -INFINITY;
        const int jb = chunk * 64;
        for (int j = 0; j < 64; j++) m = fmaxf(m, sx[(jb + j) * ROWSTR + d]);
        sred[chunk * 128 + d] = m;
    }
    __syncthreads();
    if (tid < 128) {
        float m = fmaxf(fmaxf(sred[tid], sred[128 + tid]),
                        fmaxf(sred[256 + tid], sred[384 + tid]));
        out[(size_t)bm * 256 + tid]       = m;
        out[(size_t)bm * 256 + 128 + tid] = m;
    }
}

extern "C" void kernel_launch(void* const* d_in, const int* in_sizes, int n_in,
                              void* d_out, int out_size)
{
    const int INPUT_ELEMS = 8 * 128 * 256 * 8;   // 2,097,152
    const float* inp = nullptr;
    const float* w[16];
    int wi = 0;
    for (int i = 0; i < n_in; i++) {
        if (in_sizes[i] == INPUT_ELEMS) inp = (const float*)d_in[i];
        else if (wi < 16)               w[wi++] = (const float*)d_in[i];
    }

    cudaFuncSetAttribute(localgraph_fused_kernel,
                         cudaFuncAttributeMaxDynamicSharedMemorySize, SMEM_BYTES);

    localgraph_fused_kernel<<<8 * 128, NTHREADS, SMEM_BYTES>>>(
        inp,
        w[0],  w[1],  w[2],  w[3],
        w[4],  w[5],  w[6],  w[7],
        w[8],  w[9],  w[10], w[11],
        w[12], w[13], w[14], w[15],
        (float*)d_out);
}

// round 4
// speedup vs baseline: 1.7972x; 1.0800x over previous
#include <cuda_runtime.h>
#include <math.h>

#define NTHREADS 512
#define NNODES   256
#define ROWSTR   132   // 128 + 4 pad: 16B-aligned rows, conflict-free column scans

// shared memory carve (floats)
#define X2_SZ   (NNODES * ROWSTR)        // 33792  node activations [256][132]
#define W_SZ    (16384 + 3 * 128)        // 16768  current-stage weights + b,g,be
#define RED_SZ  1536                     // top-2 partials / colmax partials
#define FIN_SZ  192                      // final m1,m2,i1 per channel
#define SMEM_FLOATS (X2_SZ + W_SZ + RED_SZ + FIN_SZ)
#define SMEM_BYTES  (SMEM_FLOATS * 4)

// Decomposition: thread t = (pair p = t>>2, quarter q = t&3).
// Owns nodes {2p, 2p+1} and channels d = 16*g + 4*q + j  (j<4).
// - weight LDS.128 amortized over 2 nodes (8 FFMA per load)
// - 4 q-lanes' weight addrs span one contiguous 64B line -> conflict-free
// - LN reduces across the 4 q-threads via shfl_xor 1,2 (same warp)

__global__ __launch_bounds__(NTHREADS, 1)
void localgraph_fused_kernel(
    const float* __restrict__ inp,
    const float* __restrict__ W0, const float* __restrict__ b0, const float* __restrict__ g0, const float* __restrict__ be0,
    const float* __restrict__ W1, const float* __restrict__ b1, const float* __restrict__ g1, const float* __restrict__ be1,
    const float* __restrict__ W2, const float* __restrict__ b2, const float* __restrict__ g2, const float* __restrict__ be2,
    const float* __restrict__ W3, const float* __restrict__ b3, const float* __restrict__ g3, const float* __restrict__ be3,
    float* __restrict__ out)
{
    extern __shared__ float smem[];
    float* sx   = smem;                 // [256][132]
    float* sw   = smem + X2_SZ;         // weights region (reused per stage)
    float* sred = sw + W_SZ;            // reduction scratch
    float* sfin = sred + RED_SZ;        // final top-2 per channel

    const int tid = threadIdx.x;
    const int bm  = blockIdx.x;         // (b*M + m)
    const int p   = tid >> 2;           // node pair 0..127
    const int q   = tid & 3;            // channel quarter
    const int co  = 4 * q;
    const int n0  = 2 * p, n1 = 2 * p + 1;
    float* row0 = sx + n0 * ROWSTR;
    float* row1 = row0 + ROWSTR;

    // ---- load input rows for both nodes (L1-cached; q-redundant is fine) ----
    float x0[8], x1[8];
    {
        const float4* pa = reinterpret_cast<const float4*>(inp + ((size_t)bm * NNODES + n0) * 8);
        float4 a = pa[0], b = pa[1], c = pa[2], d = pa[3];
        x0[0]=a.x; x0[1]=a.y; x0[2]=a.z; x0[3]=a.w;
        x0[4]=b.x; x0[5]=b.y; x0[6]=b.z; x0[7]=b.w;
        x1[0]=c.x; x1[1]=c.y; x1[2]=c.z; x1[3]=c.w;
        x1[4]=d.x; x1[5]=d.y; x1[6]=d.z; x1[7]=d.w;
    }

    // ---- stage-1 weights: W0(512) b0 g0 be0 | W1(4096) b1 g1 be1 ----
    for (int i = tid; i < 512;  i += NTHREADS) sw[i]     = W0[i];
    if (tid < 64) { sw[512+tid]=b0[tid]; sw[576+tid]=g0[tid]; sw[640+tid]=be0[tid]; }
    for (int i = tid; i < 4096; i += NTHREADS) sw[704+i] = W1[i];
    if (tid >= 64 && tid < 128) {
        int i = tid - 64;
        sw[4800+i]=b1[i]; sw[4864+i]=g1[i]; sw[4928+i]=be1[i];
    }
    __syncthreads();

    // ---- mlp0: 8 -> 64, LN, ReLU  (2 nodes x 16 channels) ----
    float h0[16], h1[16];
#pragma unroll
    for (int g = 0; g < 4; g++) {
        float4 b4 = *reinterpret_cast<const float4*>(&sw[512 + 16*g + co]);
        h0[4*g+0]=b4.x; h0[4*g+1]=b4.y; h0[4*g+2]=b4.z; h0[4*g+3]=b4.w;
        h1[4*g+0]=b4.x; h1[4*g+1]=b4.y; h1[4*g+2]=b4.z; h1[4*g+3]=b4.w;
    }
#pragma unroll
    for (int k = 0; k < 8; k++) {
        float a0 = x0[k], a1 = x1[k];
#pragma unroll
        for (int g = 0; g < 4; g++) {
            float4 w = *reinterpret_cast<const float4*>(&sw[k*64 + 16*g + co]);
            h0[4*g+0] += a0*w.x; h0[4*g+1] += a0*w.y; h0[4*g+2] += a0*w.z; h0[4*g+3] += a0*w.w;
            h1[4*g+0] += a1*w.x; h1[4*g+1] += a1*w.y; h1[4*g+2] += a1*w.z; h1[4*g+3] += a1*w.w;
        }
    }
    {   // LN(64) across quartet + ReLU, both nodes
        float s0 = 0.f, s1 = 0.f;
#pragma unroll
        for (int i = 0; i < 16; i++) { s0 += h0[i]; s1 += h1[i]; }
        s0 += __shfl_xor_sync(0xffffffffu, s0, 1); s0 += __shfl_xor_sync(0xffffffffu, s0, 2);
        s1 += __shfl_xor_sync(0xffffffffu, s1, 1); s1 += __shfl_xor_sync(0xffffffffu, s1, 2);
        float mu0 = s0 * (1.0f/64.0f), mu1 = s1 * (1.0f/64.0f);
        float v0 = 0.f, v1 = 0.f;
#pragma unroll
        for (int i = 0; i < 16; i++) {
            float d0 = h0[i]-mu0; v0 += d0*d0;
            float d1 = h1[i]-mu1; v1 += d1*d1;
        }
        v0 += __shfl_xor_sync(0xffffffffu, v0, 1); v0 += __shfl_xor_sync(0xffffffffu, v0, 2);
        v1 += __shfl_xor_sync(0xffffffffu, v1, 1); v1 += __shfl_xor_sync(0xffffffffu, v1, 2);
        float rs0 = rsqrtf(v0 * (1.0f/64.0f) + 1e-5f);
        float rs1 = rsqrtf(v1 * (1.0f/64.0f) + 1e-5f);
#pragma unroll
        for (int g = 0; g < 4; g++) {
            float4 g4  = *reinterpret_cast<const float4*>(&sw[576 + 16*g + co]);
            float4 be4 = *reinterpret_cast<const float4*>(&sw[640 + 16*g + co]);
            h0[4*g+0]=fmaxf((h0[4*g+0]-mu0)*rs0*g4.x+be4.x,0.f); h1[4*g+0]=fmaxf((h1[4*g+0]-mu1)*rs1*g4.x+be4.x,0.f);
            h0[4*g+1]=fmaxf((h0[4*g+1]-mu0)*rs0*g4.y+be4.y,0.f); h1[4*g+1]=fmaxf((h1[4*g+1]-mu1)*rs1*g4.y+be4.y,0.f);
            h0[4*g+2]=fmaxf((h0[4*g+2]-mu0)*rs0*g4.z+be4.z,0.f); h1[4*g+2]=fmaxf((h1[4*g+2]-mu1)*rs1*g4.z+be4.z,0.f);
            h0[4*g+3]=fmaxf((h0[4*g+3]-mu0)*rs0*g4.w+be4.w,0.f); h1[4*g+3]=fmaxf((h1[4*g+3]-mu1)*rs1*g4.w+be4.w,0.f);
        }
    }
#pragma unroll
    for (int g = 0; g < 4; g++) {
        *reinterpret_cast<float4*>(&row0[16*g + co]) = make_float4(h0[4*g+0],h0[4*g+1],h0[4*g+2],h0[4*g+3]);
        *reinterpret_cast<float4*>(&row1[16*g + co]) = make_float4(h1[4*g+0],h1[4*g+1],h1[4*g+2],h1[4*g+3]);
    }
    __syncwarp();

    // ---- mlp1: 64 -> 64, LN, ReLU ----
    float e0[16], e1[16];
#pragma unroll
    for (int g = 0; g < 4; g++) {
        float4 b4 = *reinterpret_cast<const float4*>(&sw[4800 + 16*g + co]);
        e0[4*g+0]=b4.x; e0[4*g+1]=b4.y; e0[4*g+2]=b4.z; e0[4*g+3]=b4.w;
        e1[4*g+0]=b4.x; e1[4*g+1]=b4.y; e1[4*g+2]=b4.z; e1[4*g+3]=b4.w;
    }
    for (int k = 0; k < 64; k += 4) {
        float4 a0 = *reinterpret_cast<const float4*>(&row0[k]);
        float4 a1 = *reinterpret_cast<const float4*>(&row1[k]);
        float av0[4] = {a0.x,a0.y,a0.z,a0.w};
        float av1[4] = {a1.x,a1.y,a1.z,a1.w};
#pragma unroll
        for (int kk = 0; kk < 4; kk++) {
            float xa = av0[kk], xb = av1[kk];
#pragma unroll
            for (int g = 0; g < 4; g++) {
                float4 w = *reinterpret_cast<const float4*>(&sw[704 + (k+kk)*64 + 16*g + co]);
                e0[4*g+0] += xa*w.x; e0[4*g+1] += xa*w.y; e0[4*g+2] += xa*w.z; e0[4*g+3] += xa*w.w;
                e1[4*g+0] += xb*w.x; e1[4*g+1] += xb*w.y; e1[4*g+2] += xb*w.z; e1[4*g+3] += xb*w.w;
            }
        }
    }
    {
        float s0 = 0.f, s1 = 0.f;
#pragma unroll
        for (int i = 0; i < 16; i++) { s0 += e0[i]; s1 += e1[i]; }
        s0 += __shfl_xor_sync(0xffffffffu, s0, 1); s0 += __shfl_xor_sync(0xffffffffu, s0, 2);
        s1 += __shfl_xor_sync(0xffffffffu, s1, 1); s1 += __shfl_xor_sync(0xffffffffu, s1, 2);
        float mu0 = s0 * (1.0f/64.0f), mu1 = s1 * (1.0f/64.0f);
        float v0 = 0.f, v1 = 0.f;
#pragma unroll
        for (int i = 0; i < 16; i++) {
            float d0 = e0[i]-mu0; v0 += d0*d0;
            float d1 = e1[i]-mu1; v1 += d1*d1;
        }
        v0 += __shfl_xor_sync(0xffffffffu, v0, 1); v0 += __shfl_xor_sync(0xffffffffu, v0, 2);
        v1 += __shfl_xor_sync(0xffffffffu, v1, 1); v1 += __shfl_xor_sync(0xffffffffu, v1, 2);
        float rs0 = rsqrtf(v0 * (1.0f/64.0f) + 1e-5f);
        float rs1 = rsqrtf(v1 * (1.0f/64.0f) + 1e-5f);
#pragma unroll
        for (int g = 0; g < 4; g++) {
            float4 g4  = *reinterpret_cast<const float4*>(&sw[4864 + 16*g + co]);
            float4 be4 = *reinterpret_cast<const float4*>(&sw[4928 + 16*g + co]);
            e0[4*g+0]=fmaxf((e0[4*g+0]-mu0)*rs0*g4.x+be4.x,0.f); e1[4*g+0]=fmaxf((e1[4*g+0]-mu1)*rs1*g4.x+be4.x,0.f);
            e0[4*g+1]=fmaxf((e0[4*g+1]-mu0)*rs0*g4.y+be4.y,0.f); e1[4*g+1]=fmaxf((e1[4*g+1]-mu1)*rs1*g4.y+be4.y,0.f);
            e0[4*g+2]=fmaxf((e0[4*g+2]-mu0)*rs0*g4.z+be4.z,0.f); e1[4*g+2]=fmaxf((e1[4*g+2]-mu1)*rs1*g4.z+be4.z,0.f);
            e0[4*g+3]=fmaxf((e0[4*g+3]-mu0)*rs0*g4.w+be4.w,0.f); e1[4*g+3]=fmaxf((e1[4*g+3]-mu1)*rs1*g4.w+be4.w,0.f);
        }
    }
    __syncwarp();                        // quartet done reading h from rows
#pragma unroll
    for (int g = 0; g < 4; g++) {
        *reinterpret_cast<float4*>(&row0[16*g + co]) = make_float4(e0[4*g+0],e0[4*g+1],e0[4*g+2],e0[4*g+3]);
        *reinterpret_cast<float4*>(&row1[16*g + co]) = make_float4(e1[4*g+0],e1[4*g+1],e1[4*g+2],e1[4*g+3]);
    }
    __syncthreads();

    // ---- exclude-self max over 256 nodes, per channel (top-2 + argmax) ----
    {
        const int ch = tid & 63, chunk = tid >> 6;   // 8 chunks x 32 nodes
        float m1 = -INFINITY, m2 = -INFINITY; int i1 = -1;
        const int jb = chunk * 32;
        for (int j = 0; j < 32; j++) {
            float v = sx[(jb + j) * ROWSTR + ch];
            if (v > m1)      { m2 = m1; m1 = v; i1 = jb + j; }
            else if (v > m2) { m2 = v; }
        }
        sred[chunk * 64 + ch]       = m1;
        sred[512 + chunk * 64 + ch] = m2;
        reinterpret_cast<int*>(sred)[1024 + chunk * 64 + ch] = i1;
    }
    __syncthreads();
    if (tid < 64) {
        float m1 = sred[tid], m2 = sred[512 + tid];
        int   i1 = reinterpret_cast<int*>(sred)[1024 + tid];
#pragma unroll
        for (int c = 1; c < 8; c++) {
            float a1 = sred[c * 64 + tid], a2 = sred[512 + c * 64 + tid];
            int   ai = reinterpret_cast<int*>(sred)[1024 + c * 64 + tid];
            if (a1 > m1) { m2 = fmaxf(m1, a2); m1 = a1; i1 = ai; }
            else         { m2 = fmaxf(m2, a1); }
        }
        sfin[tid] = m1; sfin[64 + tid] = m2;
        reinterpret_cast<int*>(sfin)[128 + tid] = i1;
    }
    __syncthreads();

    // concat: row[64+d] = max(excl_n(d), e2[n][d] - 10000); 16 ch x 2 nodes
#pragma unroll
    for (int g = 0; g < 4; g++) {
#pragma unroll
        for (int j = 0; j < 4; j++) {
            int d = 16*g + co + j;
            float m1 = sfin[d], m2 = sfin[64 + d];
            int   i1 = reinterpret_cast<int*>(sfin)[128 + d];
            float va = row0[d], vb = row1[d];
            row0[64 + d] = fmaxf((i1 == n0) ? m2 : m1, va - 10000.0f);
            row1[64 + d] = fmaxf((i1 == n1) ? m2 : m1, vb - 10000.0f);
        }
    }

    // ---- stage-2 weights: W2(16384) b2 g2 be2 ----
    for (int i = tid; i < 16384; i += NTHREADS) sw[i] = W2[i];
    if (tid < 128) { sw[16384+tid]=b2[tid]; sw[16512+tid]=g2[tid]; sw[16640+tid]=be2[tid]; }
    __syncthreads();

    // ---- mlp2 & mlp3: 128 -> 128, LN, ReLU (2 nodes x 32 channels) ----
    for (int stage = 0; stage < 2; stage++) {
        float acc0[32], acc1[32];
#pragma unroll
        for (int g = 0; g < 8; g++) {
            float4 b4 = *reinterpret_cast<const float4*>(&sw[16384 + 16*g + co]);
            acc0[4*g+0]=b4.x; acc0[4*g+1]=b4.y; acc0[4*g+2]=b4.z; acc0[4*g+3]=b4.w;
            acc1[4*g+0]=b4.x; acc1[4*g+1]=b4.y; acc1[4*g+2]=b4.z; acc1[4*g+3]=b4.w;
        }
        for (int k = 0; k < 128; k += 4) {
            float4 a0 = *reinterpret_cast<const float4*>(&row0[k]);
            float4 a1 = *reinterpret_cast<const float4*>(&row1[k]);
            float av0[4] = {a0.x,a0.y,a0.z,a0.w};
            float av1[4] = {a1.x,a1.y,a1.z,a1.w};
#pragma unroll
            for (int kk = 0; kk < 4; kk++) {
                float xa = av0[kk], xb = av1[kk];
#pragma unroll
                for (int g = 0; g < 8; g++) {
                    float4 w = *reinterpret_cast<const float4*>(&sw[(k+kk)*128 + 16*g + co]);
                    acc0[4*g+0] += xa*w.x; acc0[4*g+1] += xa*w.y; acc0[4*g+2] += xa*w.z; acc0[4*g+3] += xa*w.w;
                    acc1[4*g+0] += xb*w.x; acc1[4*g+1] += xb*w.y; acc1[4*g+2] += xb*w.z; acc1[4*g+3] += xb*w.w;
                }
            }
        }
        {
            float s0 = 0.f, s1 = 0.f;
#pragma unroll
            for (int i = 0; i < 32; i++) { s0 += acc0[i]; s1 += acc1[i]; }
            s0 += __shfl_xor_sync(0xffffffffu, s0, 1); s0 += __shfl_xor_sync(0xffffffffu, s0, 2);
            s1 += __shfl_xor_sync(0xffffffffu, s1, 1); s1 += __shfl_xor_sync(0xffffffffu, s1, 2);
            float mu0 = s0 * (1.0f/128.0f), mu1 = s1 * (1.0f/128.0f);
            float v0 = 0.f, v1 = 0.f;
#pragma unroll
            for (int i = 0; i < 32; i++) {
                float d0 = acc0[i]-mu0; v0 += d0*d0;
                float d1 = acc1[i]-mu1; v1 += d1*d1;
            }
            v0 += __shfl_xor_sync(0xffffffffu, v0, 1); v0 += __shfl_xor_sync(0xffffffffu, v0, 2);
            v1 += __shfl_xor_sync(0xffffffffu, v1, 1); v1 += __shfl_xor_sync(0xffffffffu, v1, 2);
            float rs0 = rsqrtf(v0 * (1.0f/128.0f) + 1e-5f);
            float rs1 = rsqrtf(v1 * (1.0f/128.0f) + 1e-5f);
#pragma unroll
            for (int g = 0; g < 8; g++) {
                float4 g4  = *reinterpret_cast<const float4*>(&sw[16512 + 16*g + co]);
                float4 be4 = *reinterpret_cast<const float4*>(&sw[16640 + 16*g + co]);
                acc0[4*g+0]=fmaxf((acc0[4*g+0]-mu0)*rs0*g4.x+be4.x,0.f); acc1[4*g+0]=fmaxf((acc1[4*g+0]-mu1)*rs1*g4.x+be4.x,0.f);
                acc0[4*g+1]=fmaxf((acc0[4*g+1]-mu0)*rs0*g4.y+be4.y,0.f); acc1[4*g+1]=fmaxf((acc1[4*g+1]-mu1)*rs1*g4.y+be4.y,0.f);
                acc0[4*g+2]=fmaxf((acc0[4*g+2]-mu0)*rs0*g4.z+be4.z,0.f); acc1[4*g+2]=fmaxf((acc1[4*g+2]-mu1)*rs1*g4.z+be4.z,0.f);
                acc0[4*g+3]=fmaxf((acc0[4*g+3]-mu0)*rs0*g4.w+be4.w,0.f); acc1[4*g+3]=fmaxf((acc1[4*g+3]-mu1)*rs1*g4.w+be4.w,0.f);
            }
        }
        __syncwarp();                    // quartet done reading rows
#pragma unroll
        for (int g = 0; g < 8; g++) {
            *reinterpret_cast<float4*>(&row0[16*g + co]) = make_float4(acc0[4*g+0],acc0[4*g+1],acc0[4*g+2],acc0[4*g+3]);
            *reinterpret_cast<float4*>(&row1[16*g + co]) = make_float4(acc1[4*g+0],acc1[4*g+1],acc1[4*g+2],acc1[4*g+3]);
        }
        __syncthreads();                 // rows final; everyone done reading sw

        if (stage == 0) {
            // ---- stage-3 weights: W3 b3 g3 be3 ----
            for (int i = tid; i < 16384; i += NTHREADS) sw[i] = W3[i];
            if (tid < 128) { sw[16384+tid]=b3[tid]; sw[16512+tid]=g3[tid]; sw[16640+tid]=be3[tid]; }
            __syncthreads();
        }
    }

    // ---- final: out[:,:,d] = out[:,:,128+d] = max_n e4[n][d] ----
    {
        const int d = tid & 127, chunk = tid >> 7;   // 4 chunks x 64 nodes
        float m = -INFINITY;
        const int jb = chunk * 64;
        for (int j = 0; j < 64; j++) m = fmaxf(m, sx[(jb + j) * ROWSTR + d]);
        sred[chunk * 128 + d] = m;
    }
    __syncthreads();
    if (tid < 128) {
        float m = fmaxf(fmaxf(sred[tid], sred[128 + tid]),
                        fmaxf(sred[256 + tid], sred[384 + tid]));
        out[(size_t)bm * 256 + tid]       = m;
        out[(size_t)bm * 256 + 128 + tid] = m;
    }
}

extern "C" void kernel_launch(void* const* d_in, const int* in_sizes, int n_in,
                              void* d_out, int out_size)
{
    const int INPUT_ELEMS = 8 * 128 * 256 * 8;   // 2,097,152
    const float* inp = nullptr;
    const float* w[16];
    int wi = 0;
    for (int i = 0; i < n_in; i++) {
        if (in_sizes[i] == INPUT_ELEMS) inp = (const float*)d_in[i];
        else if (wi < 16)               w[wi++] = (const float*)d_in[i];
    }

    cudaFuncSetAttribute(localgraph_fused_kernel,
                         cudaFuncAttributeMaxDynamicSharedMemorySize, SMEM_BYTES);

    localgraph_fused_kernel<<<8 * 128, NTHREADS, SMEM_BYTES>>>(
        inp,
        w[0],  w[1],  w[2],  w[3],
        w[4],  w[5],  w[6],  w[7],
        w[8],  w[9],  w[10], w[11],
        w[12], w[13], w[14], w[15],
        (float*)d_out);
}

// round 5
// speedup vs baseline: 2.2828x; 1.2702x over previous
#include <cuda_runtime.h>
#include <math.h>

#define NTHREADS 512
#define NNODES   256
#define ROWSTR   132   // 128+4 pad: 16B-aligned rows; adjacent rows 4 banks apart

// shared memory carve (floats)
#define X2_SZ   (NNODES * ROWSTR)        // 33792  node activations [256][132]
#define W_SZ    (16384 + 3 * 128)        // 16768  current-stage weights + b,g,be
#define RED_SZ  1536                     // top-2 partials / colmax partials
#define FIN_SZ  192                      // final m1,m2,i1 per channel
#define SMEM_FLOATS (X2_SZ + W_SZ + RED_SZ + FIN_SZ)
#define SMEM_BYTES  (SMEM_FLOATS * 4)

// Decomposition: warp w owns nodes [16w,16w+16). lane = 8*g + o8.
// Thread owns nodes {16w + g + 4j : j<4} and channels {32G + 4*o8 + c}.
// - weight LDS.128: 8 o8-lanes span 128B contiguous, broadcast over g (conflict-free),
//   each load feeds 16 FFMA (4 nodes x 4 channels)
// - act LDS.128: 4 g-rows adjacent (132 floats apart -> banks 4g) conflict-free
// - LN reduces over the 8 o8-lanes: shfl_xor 1,2,4

__global__ __launch_bounds__(NTHREADS, 1)
void localgraph_fused_kernel(
    const float* __restrict__ inp,
    const float* __restrict__ W0, const float* __restrict__ b0, const float* __restrict__ g0, const float* __restrict__ be0,
    const float* __restrict__ W1, const float* __restrict__ b1, const float* __restrict__ g1, const float* __restrict__ be1,
    const float* __restrict__ W2, const float* __restrict__ b2, const float* __restrict__ g2, const float* __restrict__ be2,
    const float* __restrict__ W3, const float* __restrict__ b3, const float* __restrict__ g3, const float* __restrict__ be3,
    float* __restrict__ out)
{
    extern __shared__ float smem[];
    float* sx   = smem;                 // [256][132]
    float* sw   = smem + X2_SZ;         // weights region (reused per stage)
    float* sred = sw + W_SZ;            // reduction scratch
    float* sfin = sred + RED_SZ;        // final top-2 per channel

    const int tid  = threadIdx.x;
    const int bm   = blockIdx.x;        // (b*M + m)
    const int lane = tid & 31;
    const int warp = tid >> 5;
    const int g    = lane >> 3;         // node subgroup 0..3
    const int o8   = lane & 7;          // channel octant
    const int co   = 4 * o8;
    const int nb   = 16 * warp + g;     // thread's nodes: nb + 4j

    float* rows[4];
#pragma unroll
    for (int j = 0; j < 4; j++) rows[j] = sx + (nb + 4*j) * ROWSTR;

    // ---- stage-1 weights: W0(512) b0 g0 be0 | W1(4096) b1 g1 be1 ----
    for (int i = tid; i < 512;  i += NTHREADS) sw[i]     = W0[i];
    if (tid < 64) { sw[512+tid]=b0[tid]; sw[576+tid]=g0[tid]; sw[640+tid]=be0[tid]; }
    for (int i = tid; i < 4096; i += NTHREADS) sw[704+i] = W1[i];
    if (tid >= 64 && tid < 128) {
        int i = tid - 64;
        sw[4800+i]=b1[i]; sw[4864+i]=g1[i]; sw[4928+i]=be1[i];
    }

    // ---- load input rows for the 4 owned nodes ----
    float x[4][8];
#pragma unroll
    for (int j = 0; j < 4; j++) {
        const float4* pa = reinterpret_cast<const float4*>(inp + ((size_t)bm * NNODES + nb + 4*j) * 8);
        float4 a = pa[0], b = pa[1];
        x[j][0]=a.x; x[j][1]=a.y; x[j][2]=a.z; x[j][3]=a.w;
        x[j][4]=b.x; x[j][5]=b.y; x[j][6]=b.z; x[j][7]=b.w;
    }
    __syncthreads();

    // ---- mlp0: 8 -> 64, LN, ReLU  (4 nodes x 8 channels: G=0..1) ----
    float h[4][8];
#pragma unroll
    for (int G = 0; G < 2; G++) {
        float4 b4 = *reinterpret_cast<const float4*>(&sw[512 + 32*G + co]);
#pragma unroll
        for (int j = 0; j < 4; j++) {
            h[j][4*G+0]=b4.x; h[j][4*G+1]=b4.y; h[j][4*G+2]=b4.z; h[j][4*G+3]=b4.w;
        }
    }
#pragma unroll
    for (int k = 0; k < 8; k++) {
#pragma unroll
        for (int G = 0; G < 2; G++) {
            float4 w = *reinterpret_cast<const float4*>(&sw[k*64 + 32*G + co]);
#pragma unroll
            for (int j = 0; j < 4; j++) {
                float a = x[j][k];
                h[j][4*G+0] += a*w.x; h[j][4*G+1] += a*w.y;
                h[j][4*G+2] += a*w.z; h[j][4*G+3] += a*w.w;
            }
        }
    }
#pragma unroll
    for (int j = 0; j < 4; j++) {
        float s = 0.f;
#pragma unroll
        for (int i = 0; i < 8; i++) s += h[j][i];
        s += __shfl_xor_sync(0xffffffffu, s, 1);
        s += __shfl_xor_sync(0xffffffffu, s, 2);
        s += __shfl_xor_sync(0xffffffffu, s, 4);
        float mu = s * (1.0f/64.0f), v = 0.f;
#pragma unroll
        for (int i = 0; i < 8; i++) { float d = h[j][i]-mu; v += d*d; }
        v += __shfl_xor_sync(0xffffffffu, v, 1);
        v += __shfl_xor_sync(0xffffffffu, v, 2);
        v += __shfl_xor_sync(0xffffffffu, v, 4);
        float rs = rsqrtf(v * (1.0f/64.0f) + 1e-5f);
#pragma unroll
        for (int G = 0; G < 2; G++) {
            float4 g4  = *reinterpret_cast<const float4*>(&sw[576 + 32*G + co]);
            float4 be4 = *reinterpret_cast<const float4*>(&sw[640 + 32*G + co]);
            float4 r;
            r.x = fmaxf((h[j][4*G+0]-mu)*rs*g4.x + be4.x, 0.f);
            r.y = fmaxf((h[j][4*G+1]-mu)*rs*g4.y + be4.y, 0.f);
            r.z = fmaxf((h[j][4*G+2]-mu)*rs*g4.z + be4.z, 0.f);
            r.w = fmaxf((h[j][4*G+3]-mu)*rs*g4.w + be4.w, 0.f);
            *reinterpret_cast<float4*>(&rows[j][32*G + co]) = r;
        }
    }
    __syncwarp();

    // ---- mlp1: 64 -> 64, LN, ReLU ----
    float e[4][8];
#pragma unroll
    for (int G = 0; G < 2; G++) {
        float4 b4 = *reinterpret_cast<const float4*>(&sw[4800 + 32*G + co]);
#pragma unroll
        for (int j = 0; j < 4; j++) {
            e[j][4*G+0]=b4.x; e[j][4*G+1]=b4.y; e[j][4*G+2]=b4.z; e[j][4*G+3]=b4.w;
        }
    }
    for (int k = 0; k < 64; k += 4) {
        float4 a4[4];
#pragma unroll
        for (int j = 0; j < 4; j++) a4[j] = *reinterpret_cast<const float4*>(&rows[j][k]);
        float av[4][4];
#pragma unroll
        for (int j = 0; j < 4; j++) { av[j][0]=a4[j].x; av[j][1]=a4[j].y; av[j][2]=a4[j].z; av[j][3]=a4[j].w; }
#pragma unroll
        for (int kk = 0; kk < 4; kk++) {
#pragma unroll
            for (int G = 0; G < 2; G++) {
                float4 w = *reinterpret_cast<const float4*>(&sw[704 + (k+kk)*64 + 32*G + co]);
#pragma unroll
                for (int j = 0; j < 4; j++) {
                    float a = av[j][kk];
                    e[j][4*G+0] += a*w.x; e[j][4*G+1] += a*w.y;
                    e[j][4*G+2] += a*w.z; e[j][4*G+3] += a*w.w;
                }
            }
        }
    }
    __syncwarp();                        // done reading mlp0 rows
#pragma unroll
    for (int j = 0; j < 4; j++) {
        float s = 0.f;
#pragma unroll
        for (int i = 0; i < 8; i++) s += e[j][i];
        s += __shfl_xor_sync(0xffffffffu, s, 1);
        s += __shfl_xor_sync(0xffffffffu, s, 2);
        s += __shfl_xor_sync(0xffffffffu, s, 4);
        float mu = s * (1.0f/64.0f), v = 0.f;
#pragma unroll
        for (int i = 0; i < 8; i++) { float d = e[j][i]-mu; v += d*d; }
        v += __shfl_xor_sync(0xffffffffu, v, 1);
        v += __shfl_xor_sync(0xffffffffu, v, 2);
        v += __shfl_xor_sync(0xffffffffu, v, 4);
        float rs = rsqrtf(v * (1.0f/64.0f) + 1e-5f);
#pragma unroll
        for (int G = 0; G < 2; G++) {
            float4 g4  = *reinterpret_cast<const float4*>(&sw[4864 + 32*G + co]);
            float4 be4 = *reinterpret_cast<const float4*>(&sw[4928 + 32*G + co]);
            float4 r;
            r.x = fmaxf((e[j][4*G+0]-mu)*rs*g4.x + be4.x, 0.f);
            r.y = fmaxf((e[j][4*G+1]-mu)*rs*g4.y + be4.y, 0.f);
            r.z = fmaxf((e[j][4*G+2]-mu)*rs*g4.z + be4.z, 0.f);
            r.w = fmaxf((e[j][4*G+3]-mu)*rs*g4.w + be4.w, 0.f);
            *reinterpret_cast<float4*>(&rows[j][32*G + co]) = r;
        }
    }
    __syncthreads();

    // ---- exclude-self max over 256 nodes, per channel (top-2 + argmax) ----
    {
        const int ch = tid & 63, chunk = tid >> 6;   // 8 chunks x 32 nodes
        float m1 = -INFINITY, m2 = -INFINITY; int i1 = -1;
        const int jb = chunk * 32;
        for (int j = 0; j < 32; j++) {
            float v = sx[(jb + j) * ROWSTR + ch];
            if (v > m1)      { m2 = m1; m1 = v; i1 = jb + j; }
            else if (v > m2) { m2 = v; }
        }
        sred[chunk * 64 + ch]       = m1;
        sred[512 + chunk * 64 + ch] = m2;
        reinterpret_cast<int*>(sred)[1024 + chunk * 64 + ch] = i1;
    }
    __syncthreads();
    if (tid < 64) {
        float m1 = sred[tid], m2 = sred[512 + tid];
        int   i1 = reinterpret_cast<int*>(sred)[1024 + tid];
#pragma unroll
        for (int c = 1; c < 8; c++) {
            float a1 = sred[c * 64 + tid], a2 = sred[512 + c * 64 + tid];
            int   ai = reinterpret_cast<int*>(sred)[1024 + c * 64 + tid];
            if (a1 > m1) { m2 = fmaxf(m1, a2); m1 = a1; i1 = ai; }
            else         { m2 = fmaxf(m2, a1); }
        }
        sfin[tid] = m1; sfin[64 + tid] = m2;
        reinterpret_cast<int*>(sfin)[128 + tid] = i1;
    }
    __syncthreads();

    // concat: row[64+d] = max(excl_n(d), e2[n][d] - 10000); 4 nodes x 8 ch
#pragma unroll
    for (int G = 0; G < 2; G++) {
#pragma unroll
        for (int c = 0; c < 4; c++) {
            int d = 32*G + co + c;
            float m1 = sfin[d], m2 = sfin[64 + d];
            int   i1 = reinterpret_cast<int*>(sfin)[128 + d];
#pragma unroll
            for (int j = 0; j < 4; j++) {
                int nj = nb + 4*j;
                float v = rows[j][d];
                rows[j][64 + d] = fmaxf((i1 == nj) ? m2 : m1, v - 10000.0f);
            }
        }
    }

    // ---- stage-2 weights: W2(16384) b2 g2 be2 ----
    for (int i = tid; i < 16384; i += NTHREADS) sw[i] = W2[i];
    if (tid < 128) { sw[16384+tid]=b2[tid]; sw[16512+tid]=g2[tid]; sw[16640+tid]=be2[tid]; }
    __syncthreads();

    // ---- mlp2 & mlp3: 128 -> 128, LN, ReLU (4 nodes x 16 channels: G=0..3) ----
    for (int stage = 0; stage < 2; stage++) {
        float acc[4][16];
#pragma unroll
        for (int G = 0; G < 4; G++) {
            float4 b4 = *reinterpret_cast<const float4*>(&sw[16384 + 32*G + co]);
#pragma unroll
            for (int j = 0; j < 4; j++) {
                acc[j][4*G+0]=b4.x; acc[j][4*G+1]=b4.y; acc[j][4*G+2]=b4.z; acc[j][4*G+3]=b4.w;
            }
        }
        for (int k = 0; k < 128; k += 4) {
            float4 a4[4];
#pragma unroll
            for (int j = 0; j < 4; j++) a4[j] = *reinterpret_cast<const float4*>(&rows[j][k]);
            float av[4][4];
#pragma unroll
            for (int j = 0; j < 4; j++) { av[j][0]=a4[j].x; av[j][1]=a4[j].y; av[j][2]=a4[j].z; av[j][3]=a4[j].w; }
#pragma unroll
            for (int kk = 0; kk < 4; kk++) {
#pragma unroll
                for (int G = 0; G < 4; G++) {
                    float4 w = *reinterpret_cast<const float4*>(&sw[(k+kk)*128 + 32*G + co]);
#pragma unroll
                    for (int j = 0; j < 4; j++) {
                        float a = av[j][kk];
                        acc[j][4*G+0] += a*w.x; acc[j][4*G+1] += a*w.y;
                        acc[j][4*G+2] += a*w.z; acc[j][4*G+3] += a*w.w;
                    }
                }
            }
        }
        __syncwarp();                    // warp done reading its rows
#pragma unroll
        for (int j = 0; j < 4; j++) {
            float s = 0.f;
#pragma unroll
            for (int i = 0; i < 16; i++) s += acc[j][i];
            s += __shfl_xor_sync(0xffffffffu, s, 1);
            s += __shfl_xor_sync(0xffffffffu, s, 2);
            s += __shfl_xor_sync(0xffffffffu, s, 4);
            float mu = s * (1.0f/128.0f), v = 0.f;
#pragma unroll
            for (int i = 0; i < 16; i++) { float d = acc[j][i]-mu; v += d*d; }
            v += __shfl_xor_sync(0xffffffffu, v, 1);
            v += __shfl_xor_sync(0xffffffffu, v, 2);
            v += __shfl_xor_sync(0xffffffffu, v, 4);
            float rs = rsqrtf(v * (1.0f/128.0f) + 1e-5f);
#pragma unroll
            for (int G = 0; G < 4; G++) {
                float4 g4  = *reinterpret_cast<const float4*>(&sw[16512 + 32*G + co]);
                float4 be4 = *reinterpret_cast<const float4*>(&sw[16640 + 32*G + co]);
                float4 r;
                r.x = fmaxf((acc[j][4*G+0]-mu)*rs*g4.x + be4.x, 0.f);
                r.y = fmaxf((acc[j][4*G+1]-mu)*rs*g4.y + be4.y, 0.f);
                r.z = fmaxf((acc[j][4*G+2]-mu)*rs*g4.z + be4.z, 0.f);
                r.w = fmaxf((acc[j][4*G+3]-mu)*rs*g4.w + be4.w, 0.f);
                *reinterpret_cast<float4*>(&rows[j][32*G + co]) = r;
            }
        }
        __syncthreads();                 // rows final; everyone done reading sw

        if (stage == 0) {
            // ---- stage-3 weights: W3 b3 g3 be3 ----
            for (int i = tid; i < 16384; i += NTHREADS) sw[i] = W3[i];
            if (tid < 128) { sw[16384+tid]=b3[tid]; sw[16512+tid]=g3[tid]; sw[16640+tid]=be3[tid]; }
            __syncthreads();
        }
    }

    // ---- final: out[:,:,d] = out[:,:,128+d] = max_n e4[n][d] ----
    {
        const int d = tid & 127, chunk = tid >> 7;   // 4 chunks x 64 nodes
        float m = -INFINITY;
        const int jb = chunk * 64;
        for (int j = 0; j < 64; j++) m = fmaxf(m, sx[(jb + j) * ROWSTR + d]);
        sred[chunk * 128 + d] = m;
    }
    __syncthreads();
    if (tid < 128) {
        float m = fmaxf(fmaxf(sred[tid], sred[128 + tid]),
                        fmaxf(sred[256 + tid], sred[384 + tid]));
        out[(size_t)bm * 256 + tid]       = m;
        out[(size_t)bm * 256 + 128 + tid] = m;
    }
}

extern "C" void kernel_launch(void* const* d_in, const int* in_sizes, int n_in,
                              void* d_out, int out_size)
{
    const int INPUT_ELEMS = 8 * 128 * 256 * 8;   // 2,097,152
    const float* inp = nullptr;
    const float* w[16];
    int wi = 0;
    for (int i = 0; i < n_in; i++) {
        if (in_sizes[i] == INPUT_ELEMS) inp = (const float*)d_in[i];
        else if (wi < 16)               w[wi++] = (const float*)d_in[i];
    }

    cudaFuncSetAttribute(localgraph_fused_kernel,
                         cudaFuncAttributeMaxDynamicSharedMemorySize, SMEM_BYTES);

    localgraph_fused_kernel<<<8 * 128, NTHREADS, SMEM_BYTES>>>(
        inp,
        w[0],  w[1],  w[2],  w[3],
        w[4],  w[5],  w[6],  w[7],
        w[8],  w[9],  w[10], w[11],
        w[12], w[13], w[14], w[15],
        (float*)d_out);
}

// round 9
// speedup vs baseline: 4.0415x; 1.7704x over previous
#include <cuda_runtime.h>
#include <cuda_bf16.h>
#include <math.h>
#include <stdint.h>

#define NTHREADS 512
#define SXSTR 68            // fp32 stage-1 row stride (floats)
#define ASTR_B 272          // bf16 row stride in BYTES (136 bf16; 272%16==0 for ldmatrix)

// ---- byte offsets ----
#define AH_B 0              // A_hi  [256][136] bf16 = 69632 B
#define AL_B 69632          // A_lo
#define WH_B 139264         // W_hi  [128][136] bf16 = 34816 B
#define WL_B 174080         // W_lo  (ends 208896)
// ---- float offsets ----
#define SX_F   34816        // fp32 [256][68] overlay on W region (stage 1 only)
#define PAR2_F 52224        // b2|g2|be2 (384 floats)
#define PAR3_F 52608        // b3|g3|be3
#define SRED_F 52992        // 1536: top2 partials / LN psums
#define SFIN_F 54528        // 192: final top-2 per channel
#define WMAX_F 54720        // 1024: per-warp column maxima
#define SMEM_FLOATS 55744
#define SMEM_BYTES (SMEM_FLOATS*4)   // 222976 < 227KB cap

__device__ __forceinline__ uint32_t smem_u32(const void* p) {
    uint32_t a;
    asm("{ .reg .u64 t; cvta.to.shared.u64 t, %1; cvt.u32.u64 %0, t; }" : "=r"(a) : "l"(p));
    return a;
}
__device__ __forceinline__ void ldm4(uint32_t& r0, uint32_t& r1, uint32_t& r2, uint32_t& r3, uint32_t a) {
    asm volatile("ldmatrix.sync.aligned.m8n8.x4.shared.b16 {%0,%1,%2,%3}, [%4];"
                 : "=r"(r0), "=r"(r1), "=r"(r2), "=r"(r3) : "r"(a));
}
__device__ __forceinline__ void mma16816(float* c, const uint32_t* A, const uint32_t* B) {
    asm volatile("mma.sync.aligned.m16n8k16.row.col.f32.bf16.bf16.f32 "
                 "{%0,%1,%2,%3},{%4,%5,%6,%7},{%8,%9},{%0,%1,%2,%3};"
                 : "+f"(c[0]), "+f"(c[1]), "+f"(c[2]), "+f"(c[3])
                 : "r"(A[0]), "r"(A[1]), "r"(A[2]), "r"(A[3]), "r"(B[0]), "r"(B[1]));
}
__device__ __forceinline__ uint32_t pack2(float a, float b) {
    __nv_bfloat162 t = __floats2bfloat162_rn(a, b);
    uint32_t r; memcpy(&r, &t, 4); return r;
}

__global__ __launch_bounds__(NTHREADS, 1)
void localgraph_fused_kernel(
    const float* __restrict__ inp,
    const float* __restrict__ W0, const float* __restrict__ b0, const float* __restrict__ g0, const float* __restrict__ be0,
    const float* __restrict__ W1, const float* __restrict__ b1, const float* __restrict__ g1, const float* __restrict__ be1,
    const float* __restrict__ W2, const float* __restrict__ b2, const float* __restrict__ g2, const float* __restrict__ be2,
    const float* __restrict__ W3, const float* __restrict__ b3, const float* __restrict__ g3, const float* __restrict__ be3,
    float* __restrict__ out)
{
    extern __shared__ float smem[];
    char*  smc  = reinterpret_cast<char*>(smem);
    float* sx   = smem + SX_F;          // [256][68] fp32 (stage 1)
    float* swf  = smem;                 // stage-1 weights overlay (in A_hi region)
    float* par2 = smem + PAR2_F;
    float* par3 = smem + PAR3_F;
    float* sred = smem + SRED_F;
    float* sfin = smem + SFIN_F;
    float* wmax = smem + WMAX_F;

    const uint32_t smb = smem_u32(smem);
    const int tid  = threadIdx.x;
    const int bm   = blockIdx.x;
    const int lane = tid & 31;
    const int w    = tid >> 5;

    // ======== STAGE 1 (scalar, Round-5 structure, stride 68) ========
    const int g1i = lane >> 3;          // node subgroup
    const int o8  = lane & 7;           // channel octant
    const int co  = 4 * o8;
    const int nb  = 16 * w + g1i;
    float* rows[4];
#pragma unroll
    for (int j = 0; j < 4; j++) rows[j] = sx + (nb + 4*j) * SXSTR;

    for (int i = tid; i < 512;  i += NTHREADS) swf[i]     = W0[i];
    if (tid < 64) { swf[512+tid]=b0[tid]; swf[576+tid]=g0[tid]; swf[640+tid]=be0[tid]; }
    for (int i = tid; i < 4096; i += NTHREADS) swf[704+i] = W1[i];
    if (tid >= 64 && tid < 128) {
        int i = tid - 64;
        swf[4800+i]=b1[i]; swf[4864+i]=g1[i]; swf[4928+i]=be1[i];
    }

    float x[4][8];
#pragma unroll
    for (int j = 0; j < 4; j++) {
        const float4* pa = reinterpret_cast<const float4*>(inp + ((size_t)bm * 256 + nb + 4*j) * 8);
        float4 a = pa[0], b = pa[1];
        x[j][0]=a.x; x[j][1]=a.y; x[j][2]=a.z; x[j][3]=a.w;
        x[j][4]=b.x; x[j][5]=b.y; x[j][6]=b.z; x[j][7]=b.w;
    }
    __syncthreads();

    // mlp0: 8 -> 64
    float h[4][8];
#pragma unroll
    for (int G = 0; G < 2; G++) {
        float4 b4 = *reinterpret_cast<const float4*>(&swf[512 + 32*G + co]);
#pragma unroll
        for (int j = 0; j < 4; j++) {
            h[j][4*G+0]=b4.x; h[j][4*G+1]=b4.y; h[j][4*G+2]=b4.z; h[j][4*G+3]=b4.w;
        }
    }
#pragma unroll
    for (int k = 0; k < 8; k++) {
#pragma unroll
        for (int G = 0; G < 2; G++) {
            float4 wv = *reinterpret_cast<const float4*>(&swf[k*64 + 32*G + co]);
#pragma unroll
            for (int j = 0; j < 4; j++) {
                float a = x[j][k];
                h[j][4*G+0] += a*wv.x; h[j][4*G+1] += a*wv.y;
                h[j][4*G+2] += a*wv.z; h[j][4*G+3] += a*wv.w;
            }
        }
    }
#pragma unroll
    for (int j = 0; j < 4; j++) {
        float sU = 0.f;
#pragma unroll
        for (int i = 0; i < 8; i++) sU += h[j][i];
        sU += __shfl_xor_sync(0xffffffffu, sU, 1);
        sU += __shfl_xor_sync(0xffffffffu, sU, 2);
        sU += __shfl_xor_sync(0xffffffffu, sU, 4);
        float mu = sU * (1.0f/64.0f), vv = 0.f;
#pragma unroll
        for (int i = 0; i < 8; i++) { float d = h[j][i]-mu; vv += d*d; }
        vv += __shfl_xor_sync(0xffffffffu, vv, 1);
        vv += __shfl_xor_sync(0xffffffffu, vv, 2);
        vv += __shfl_xor_sync(0xffffffffu, vv, 4);
        float rs = rsqrtf(vv * (1.0f/64.0f) + 1e-5f);
#pragma unroll
        for (int G = 0; G < 2; G++) {
            float4 g4  = *reinterpret_cast<const float4*>(&swf[576 + 32*G + co]);
            float4 be4 = *reinterpret_cast<const float4*>(&swf[640 + 32*G + co]);
            float4 r;
            r.x = fmaxf((h[j][4*G+0]-mu)*rs*g4.x + be4.x, 0.f);
            r.y = fmaxf((h[j][4*G+1]-mu)*rs*g4.y + be4.y, 0.f);
            r.z = fmaxf((h[j][4*G+2]-mu)*rs*g4.z + be4.z, 0.f);
            r.w = fmaxf((h[j][4*G+3]-mu)*rs*g4.w + be4.w, 0.f);
            *reinterpret_cast<float4*>(&rows[j][32*G + co]) = r;
        }
    }
    __syncwarp();

    // mlp1: 64 -> 64
    float e[4][8];
#pragma unroll
    for (int G = 0; G < 2; G++) {
        float4 b4 = *reinterpret_cast<const float4*>(&swf[4800 + 32*G + co]);
#pragma unroll
        for (int j = 0; j < 4; j++) {
            e[j][4*G+0]=b4.x; e[j][4*G+1]=b4.y; e[j][4*G+2]=b4.z; e[j][4*G+3]=b4.w;
        }
    }
    for (int k = 0; k < 64; k += 4) {
        float4 a4[4];
#pragma unroll
        for (int j = 0; j < 4; j++) a4[j] = *reinterpret_cast<const float4*>(&rows[j][k]);
        float av[4][4];
#pragma unroll
        for (int j = 0; j < 4; j++) { av[j][0]=a4[j].x; av[j][1]=a4[j].y; av[j][2]=a4[j].z; av[j][3]=a4[j].w; }
#pragma unroll
        for (int kk = 0; kk < 4; kk++) {
#pragma unroll
            for (int G = 0; G < 2; G++) {
                float4 wv = *reinterpret_cast<const float4*>(&swf[704 + (k+kk)*64 + 32*G + co]);
#pragma unroll
                for (int j = 0; j < 4; j++) {
                    float a = av[j][kk];
                    e[j][4*G+0] += a*wv.x; e[j][4*G+1] += a*wv.y;
                    e[j][4*G+2] += a*wv.z; e[j][4*G+3] += a*wv.w;
                }
            }
        }
    }
    __syncwarp();
#pragma unroll
    for (int j = 0; j < 4; j++) {
        float sU = 0.f;
#pragma unroll
        for (int i = 0; i < 8; i++) sU += e[j][i];
        sU += __shfl_xor_sync(0xffffffffu, sU, 1);
        sU += __shfl_xor_sync(0xffffffffu, sU, 2);
        sU += __shfl_xor_sync(0xffffffffu, sU, 4);
        float mu = sU * (1.0f/64.0f), vv = 0.f;
#pragma unroll
        for (int i = 0; i < 8; i++) { float d = e[j][i]-mu; vv += d*d; }
        vv += __shfl_xor_sync(0xffffffffu, vv, 1);
        vv += __shfl_xor_sync(0xffffffffu, vv, 2);
        vv += __shfl_xor_sync(0xffffffffu, vv, 4);
        float rs = rsqrtf(vv * (1.0f/64.0f) + 1e-5f);
#pragma unroll
        for (int G = 0; G < 2; G++) {
            float4 g4  = *reinterpret_cast<const float4*>(&swf[4864 + 32*G + co]);
            float4 be4 = *reinterpret_cast<const float4*>(&swf[4928 + 32*G + co]);
            float4 r;
            r.x = fmaxf((e[j][4*G+0]-mu)*rs*g4.x + be4.x, 0.f);
            r.y = fmaxf((e[j][4*G+1]-mu)*rs*g4.y + be4.y, 0.f);
            r.z = fmaxf((e[j][4*G+2]-mu)*rs*g4.z + be4.z, 0.f);
            r.w = fmaxf((e[j][4*G+3]-mu)*rs*g4.w + be4.w, 0.f);
            *reinterpret_cast<float4*>(&rows[j][32*G + co]) = r;
        }
    }
    __syncthreads();

    // top-2 + argmax per channel over 256 nodes
    {
        const int ch = tid & 63, chunk = tid >> 6;
        float m1 = -INFINITY, m2 = -INFINITY; int i1 = -1;
        const int jb = chunk * 32;
        for (int j = 0; j < 32; j++) {
            float v = sx[(jb + j) * SXSTR + ch];
            if (v > m1)      { m2 = m1; m1 = v; i1 = jb + j; }
            else if (v > m2) { m2 = v; }
        }
        sred[chunk * 64 + ch]       = m1;
        sred[512 + chunk * 64 + ch] = m2;
        reinterpret_cast<int*>(sred)[1024 + chunk * 64 + ch] = i1;
    }
    __syncthreads();
    if (tid < 64) {
        float m1 = sred[tid], m2 = sred[512 + tid];
        int   i1 = reinterpret_cast<int*>(sred)[1024 + tid];
#pragma unroll
        for (int c = 1; c < 8; c++) {
            float a1 = sred[c * 64 + tid], a2 = sred[512 + c * 64 + tid];
            int   ai = reinterpret_cast<int*>(sred)[1024 + c * 64 + tid];
            if (a1 > m1) { m2 = fmaxf(m1, a2); m1 = a1; i1 = ai; }
            else         { m2 = fmaxf(m2, a1); }
        }
        sfin[tid] = m1; sfin[64 + tid] = m2;
        reinterpret_cast<int*>(sfin)[128 + tid] = i1;
    }
    __syncthreads();

    // ======== concat -> A_hi/A_lo (bf16 split), thread = (row, half) ========
    {
        const int crow = tid >> 1, chalf = tid & 1;
        const float* sr = sx + crow * SXSTR;
        char* ah = smc + AH_B + crow * ASTR_B + chalf * 128;
        char* al = smc + AL_B + crow * ASTR_B + chalf * 128;
#pragma unroll
        for (int c = 0; c < 64; c += 2) {
            float v0, v1;
            if (chalf == 0) { v0 = sr[c]; v1 = sr[c+1]; }
            else {
                float a0 = sr[c], a1 = sr[c+1];
                int   j0 = reinterpret_cast<int*>(sfin)[128 + c];
                int   j1 = reinterpret_cast<int*>(sfin)[128 + c + 1];
                float e0x = (j0 == crow) ? sfin[64 + c]     : sfin[c];
                float e1x = (j1 == crow) ? sfin[64 + c + 1] : sfin[c + 1];
                v0 = fmaxf(e0x, a0 - 10000.0f);
                v1 = fmaxf(e1x, a1 - 10000.0f);
            }
            float h0 = __bfloat162float(__float2bfloat16(v0));
            float h1 = __bfloat162float(__float2bfloat16(v1));
            *reinterpret_cast<uint32_t*>(ah + c*2) = pack2(v0, v1);
            *reinterpret_cast<uint32_t*>(al + c*2) = pack2(v0 - h0, v1 - h1);
        }
    }
    __syncthreads();   // sx consumed; A buffers ready

    // ======== big layers: warp = (rb = w&7 node-block, cg = w>>3 col-group) ========
    const int rb = w & 7, cg = w >> 3, ob = cg * 64;
    const int lg = lane >> 3, lr = lane & 7;
    const int tq = lane & 3, tr = lane >> 2;   // quad col, row-in-tile
    // ldmatrix base offsets (row pointers 16B-aligned: 272%16==0)
    const uint32_t aoff = smb + AH_B + (uint32_t)(rb*32 + ((lg&1)<<3) + lr) * ASTR_B + ((lg>>1)<<4);
    const uint32_t boff = smb + WH_B + (uint32_t)(ob + ((lg>>1)<<3) + lr) * ASTR_B + ((lg&1)<<4);
    float* psumS = sred;          // [512]
    float* psumQ = sred + 512;    // [512]

    float acc[2][8][4];

    for (int layer = 0; layer < 2; layer++) {
        const float* par = layer ? par3 : par2;
        // ---- load W (and params) into smem bf16 hi/lo [o][k] ----
        {
            const float* Wg = layer ? W3 : W2;
            for (int i = tid; i < 16384; i += NTHREADS) {
                int k = i >> 7, o = i & 127;
                float v = Wg[i];
                float hf = __bfloat162float(__float2bfloat16(v));
                uint32_t off = (uint32_t)o * ASTR_B + k * 2;
                *reinterpret_cast<__nv_bfloat16*>(smc + WH_B + off) = __float2bfloat16(v);
                *reinterpret_cast<__nv_bfloat16*>(smc + WL_B + off) = __float2bfloat16(v - hf);
            }
            if (tid < 128) {
                float* pdst = layer ? par3 : par2;
                pdst[tid]       = layer ? b3[tid]  : b2[tid];
                pdst[128 + tid] = layer ? g3[tid]  : g2[tid];
                pdst[256 + tid] = layer ? be3[tid] : be2[tid];
            }
        }
        __syncthreads();

        // ---- MMA: C[32 nodes][64 outs] via split-bf16 (hi*hi + hi*lo + lo*hi) ----
#pragma unroll
        for (int mt = 0; mt < 2; mt++)
#pragma unroll
            for (int nt = 0; nt < 8; nt++)
#pragma unroll
                for (int q = 0; q < 4; q++) acc[mt][nt][q] = 0.f;

        for (int ks = 0; ks < 8; ks++) {
            const uint32_t kb = (uint32_t)ks * 32;
            uint32_t Ah[2][4], Al[2][4];
            ldm4(Ah[0][0], Ah[0][1], Ah[0][2], Ah[0][3], aoff + kb);
            ldm4(Ah[1][0], Ah[1][1], Ah[1][2], Ah[1][3], aoff + 16*ASTR_B + kb);
            ldm4(Al[0][0], Al[0][1], Al[0][2], Al[0][3], aoff + (AL_B - AH_B) + kb);
            ldm4(Al[1][0], Al[1][1], Al[1][2], Al[1][3], aoff + (AL_B - AH_B) + 16*ASTR_B + kb);
#pragma unroll
            for (int p = 0; p < 4; p++) {
                uint32_t Bh[4], Bl[4];
                ldm4(Bh[0], Bh[1], Bh[2], Bh[3], boff + (uint32_t)p*16*ASTR_B + kb);
                ldm4(Bl[0], Bl[1], Bl[2], Bl[3], boff + (WL_B - WH_B) + (uint32_t)p*16*ASTR_B + kb);
#pragma unroll
                for (int mt = 0; mt < 2; mt++) {
                    mma16816(acc[mt][2*p],   Ah[mt], Bh);
                    mma16816(acc[mt][2*p],   Ah[mt], Bl);
                    mma16816(acc[mt][2*p],   Al[mt], Bh);
                    mma16816(acc[mt][2*p+1], Ah[mt], Bh + 2);
                    mma16816(acc[mt][2*p+1], Ah[mt], Bl + 2);
                    mma16816(acc[mt][2*p+1], Al[mt], Bh + 2);
                }
            }
        }

        // ---- epilogue: bias, LN partial sums (per node, per col-group) ----
        float rS[2][2] = {{0.f,0.f},{0.f,0.f}}, rQ[2][2] = {{0.f,0.f},{0.f,0.f}};
#pragma unroll
        for (int mt = 0; mt < 2; mt++) {
#pragma unroll
            for (int nt = 0; nt < 8; nt++) {
                int col0 = ob + nt*8 + 2*tq;
                float2 bb = *reinterpret_cast<const float2*>(&par[col0]);
                float v00 = acc[mt][nt][0] + bb.x, v01 = acc[mt][nt][1] + bb.y;
                float v10 = acc[mt][nt][2] + bb.x, v11 = acc[mt][nt][3] + bb.y;
                acc[mt][nt][0]=v00; acc[mt][nt][1]=v01; acc[mt][nt][2]=v10; acc[mt][nt][3]=v11;
                rS[mt][0]+=v00+v01; rS[mt][1]+=v10+v11;
                rQ[mt][0]+=v00*v00+v01*v01; rQ[mt][1]+=v10*v10+v11*v11;
            }
        }
#pragma unroll
        for (int mt = 0; mt < 2; mt++)
#pragma unroll
            for (int rh = 0; rh < 2; rh++) {
                rS[mt][rh] += __shfl_xor_sync(0xffffffffu, rS[mt][rh], 1);
                rS[mt][rh] += __shfl_xor_sync(0xffffffffu, rS[mt][rh], 2);
                rQ[mt][rh] += __shfl_xor_sync(0xffffffffu, rQ[mt][rh], 1);
                rQ[mt][rh] += __shfl_xor_sync(0xffffffffu, rQ[mt][rh], 2);
            }
        if (tq == 0) {
#pragma unroll
            for (int mt = 0; mt < 2; mt++)
#pragma unroll
                for (int rh = 0; rh < 2; rh++) {
                    int node = rb*32 + mt*16 + rh*8 + tr;
                    psumS[node*2 + cg] = rS[mt][rh];
                    psumQ[node*2 + cg] = rQ[mt][rh];
                }
        }
        __syncthreads();

        float muv[2][2], rsv[2][2];
#pragma unroll
        for (int mt = 0; mt < 2; mt++)
#pragma unroll
            for (int rh = 0; rh < 2; rh++) {
                int node = rb*32 + mt*16 + rh*8 + tr;
                float S = psumS[node*2] + psumS[node*2+1];
                float Q = psumQ[node*2] + psumQ[node*2+1];
                float mu = S * (1.0f/128.0f);
                muv[mt][rh] = mu;
                rsv[mt][rh] = rsqrtf(Q * (1.0f/128.0f) - mu*mu + 1e-5f);
            }

        if (layer == 0) {
            // normalize + ReLU, write as next-layer A (bf16 hi/lo)
#pragma unroll
            for (int mt = 0; mt < 2; mt++) {
#pragma unroll
                for (int nt = 0; nt < 8; nt++) {
                    int col0 = ob + nt*8 + 2*tq;
                    float2 gg = *reinterpret_cast<const float2*>(&par[128 + col0]);
                    float2 bb = *reinterpret_cast<const float2*>(&par[256 + col0]);
                    int row0 = rb*32 + mt*16 + tr;
                    float v00 = fmaxf((acc[mt][nt][0]-muv[mt][0])*rsv[mt][0]*gg.x + bb.x, 0.f);
                    float v01 = fmaxf((acc[mt][nt][1]-muv[mt][0])*rsv[mt][0]*gg.y + bb.y, 0.f);
                    float v10 = fmaxf((acc[mt][nt][2]-muv[mt][1])*rsv[mt][1]*gg.x + bb.x, 0.f);
                    float v11 = fmaxf((acc[mt][nt][3]-muv[mt][1])*rsv[mt][1]*gg.y + bb.y, 0.f);
                    float h00 = __bfloat162float(__float2bfloat16(v00));
                    float h01 = __bfloat162float(__float2bfloat16(v01));
                    float h10 = __bfloat162float(__float2bfloat16(v10));
                    float h11 = __bfloat162float(__float2bfloat16(v11));
                    uint32_t off0 = (uint32_t)row0 * ASTR_B + col0*2;
                    uint32_t off1 = off0 + 8*ASTR_B;
                    *reinterpret_cast<uint32_t*>(smc + AH_B + off0) = pack2(v00, v01);
                    *reinterpret_cast<uint32_t*>(smc + AH_B + off1) = pack2(v10, v11);
                    *reinterpret_cast<uint32_t*>(smc + AL_B + off0) = pack2(v00 - h00, v01 - h01);
                    *reinterpret_cast<uint32_t*>(smc + AL_B + off1) = pack2(v10 - h10, v11 - h11);
                }
            }
            __syncthreads();   // A ready; W2 reads done -> W3 load next iter
        } else {
            // normalize + ReLU, column max over warp's 32 nodes
            float cm[8][2];
#pragma unroll
            for (int nt = 0; nt < 8; nt++) { cm[nt][0] = -INFINITY; cm[nt][1] = -INFINITY; }
#pragma unroll
            for (int mt = 0; mt < 2; mt++) {
#pragma unroll
                for (int nt = 0; nt < 8; nt++) {
                    int col0 = ob + nt*8 + 2*tq;
                    float2 gg = *reinterpret_cast<const float2*>(&par[128 + col0]);
                    float2 bb = *reinterpret_cast<const float2*>(&par[256 + col0]);
                    float v00 = fmaxf((acc[mt][nt][0]-muv[mt][0])*rsv[mt][0]*gg.x + bb.x, 0.f);
                    float v01 = fmaxf((acc[mt][nt][1]-muv[mt][0])*rsv[mt][0]*gg.y + bb.y, 0.f);
                    float v10 = fmaxf((acc[mt][nt][2]-muv[mt][1])*rsv[mt][1]*gg.x + bb.x, 0.f);
                    float v11 = fmaxf((acc[mt][nt][3]-muv[mt][1])*rsv[mt][1]*gg.y + bb.y, 0.f);
                    cm[nt][0] = fmaxf(cm[nt][0], fmaxf(v00, v10));
                    cm[nt][1] = fmaxf(cm[nt][1], fmaxf(v01, v11));
                }
            }
#pragma unroll
            for (int nt = 0; nt < 8; nt++)
#pragma unroll
                for (int q = 0; q < 2; q++) {
                    cm[nt][q] = fmaxf(cm[nt][q], __shfl_xor_sync(0xffffffffu, cm[nt][q], 4));
                    cm[nt][q] = fmaxf(cm[nt][q], __shfl_xor_sync(0xffffffffu, cm[nt][q], 8));
                    cm[nt][q] = fmaxf(cm[nt][q], __shfl_xor_sync(0xffffffffu, cm[nt][q], 16));
                }
            if (tr == 0) {
#pragma unroll
                for (int nt = 0; nt < 8; nt++) {
                    wmax[w*64 + nt*8 + 2*tq]     = cm[nt][0];
                    wmax[w*64 + nt*8 + 2*tq + 1] = cm[nt][1];
                }
            }
        }
    }
    __syncthreads();

    // ---- final reduce: out[d] = out[128+d] = max over 8 node-block warps ----
    if (tid < 128) {
        int cgd = tid >> 6, dd = tid & 63;
        float m = -INFINITY;
#pragma unroll
        for (int i = 0; i < 8; i++) m = fmaxf(m, wmax[(cgd*8 + i)*64 + dd]);
        out[(size_t)bm * 256 + cgd*64 + dd]       = m;
        out[(size_t)bm * 256 + 128 + cgd*64 + dd] = m;
    }
}

extern "C" void kernel_launch(void* const* d_in, const int* in_sizes, int n_in,
                              void* d_out, int out_size)
{
    const int INPUT_ELEMS = 8 * 128 * 256 * 8;   // 2,097,152
    const float* inp = nullptr;
    const float* wt[16];
    int wi = 0;
    for (int i = 0; i < n_in; i++) {
        if (in_sizes[i] == INPUT_ELEMS) inp = (const float*)d_in[i];
        else if (wi < 16)               wt[wi++] = (const float*)d_in[i];
    }

    cudaFuncSetAttribute(localgraph_fused_kernel,
                         cudaFuncAttributeMaxDynamicSharedMemorySize, SMEM_BYTES);

    localgraph_fused_kernel<<<8 * 128, NTHREADS, SMEM_BYTES>>>(
        inp,
        wt[0],  wt[1],  wt[2],  wt[3],
        wt[4],  wt[5],  wt[6],  wt[7],
        wt[8],  wt[9],  wt[10], wt[11],
        wt[12], wt[13], wt[14], wt[15],
        (float*)d_out);
}

// round 10
// speedup vs baseline: 4.4970x; 1.1127x over previous
#include <cuda_runtime.h>
#include <cuda_bf16.h>
#include <math.h>
#include <stdint.h>

#define NTHREADS 512
#define SXSTR 68            // fp32 stage-1 row stride (floats)
#define ASTR_B 272          // bf16 row stride in BYTES (136 bf16; 272%16==0 for ldmatrix)

// ---- byte offsets ----
#define AH_B 0              // A_hi  [256][136] bf16 = 69632 B
#define AL_B 69632          // A_lo
#define WH_B 139264         // W_hi  [128 k-rows][136 bf16] = 34816 B  (K-MAJOR)
#define WL_B 174080         // W_lo  (ends 208896)
// ---- float offsets ----
#define SX_F   34816        // fp32 [256][68] overlay on W region (stage 1 only)
#define PAR2_F 52224        // b2|g2|be2 (384 floats)
#define PAR3_F 52608        // b3|g3|be3
#define SRED_F 52992        // 1536: top2 partials / LN psums
#define SFIN_F 54528        // 192: final top-2 per channel
#define WMAX_F 54720        // 1024: per-warp column maxima
#define SMEM_FLOATS 55744
#define SMEM_BYTES (SMEM_FLOATS*4)   // 222976 < 227KB cap

__device__ __forceinline__ uint32_t smem_u32(const void* p) {
    uint32_t a;
    asm("{ .reg .u64 t; cvta.to.shared.u64 t, %1; cvt.u32.u64 %0, t; }" : "=r"(a) : "l"(p));
    return a;
}
__device__ __forceinline__ void ldm4(uint32_t& r0, uint32_t& r1, uint32_t& r2, uint32_t& r3, uint32_t a) {
    asm volatile("ldmatrix.sync.aligned.m8n8.x4.shared.b16 {%0,%1,%2,%3}, [%4];"
                 : "=r"(r0), "=r"(r1), "=r"(r2), "=r"(r3) : "r"(a));
}
__device__ __forceinline__ void ldm4t(uint32_t& r0, uint32_t& r1, uint32_t& r2, uint32_t& r3, uint32_t a) {
    asm volatile("ldmatrix.sync.aligned.m8n8.x4.trans.shared.b16 {%0,%1,%2,%3}, [%4];"
                 : "=r"(r0), "=r"(r1), "=r"(r2), "=r"(r3) : "r"(a));
}
__device__ __forceinline__ void mma16816(float* c, const uint32_t* A, const uint32_t* B) {
    asm volatile("mma.sync.aligned.m16n8k16.row.col.f32.bf16.bf16.f32 "
                 "{%0,%1,%2,%3},{%4,%5,%6,%7},{%8,%9},{%0,%1,%2,%3};"
                 : "+f"(c[0]), "+f"(c[1]), "+f"(c[2]), "+f"(c[3])
                 : "r"(A[0]), "r"(A[1]), "r"(A[2]), "r"(A[3]), "r"(B[0]), "r"(B[1]));
}
__device__ __forceinline__ uint32_t pack2(float a, float b) {
    __nv_bfloat162 t = __floats2bfloat162_rn(a, b);
    uint32_t r; memcpy(&r, &t, 4); return r;
}
__device__ __forceinline__ float bfr(float v) {
    return __bfloat162float(__float2bfloat16(v));
}

__global__ __launch_bounds__(NTHREADS, 1)
void localgraph_fused_kernel(
    const float* __restrict__ inp,
    const float* __restrict__ W0, const float* __restrict__ b0, const float* __restrict__ g0, const float* __restrict__ be0,
    const float* __restrict__ W1, const float* __restrict__ b1, const float* __restrict__ g1, const float* __restrict__ be1,
    const float* __restrict__ W2, const float* __restrict__ b2, const float* __restrict__ g2, const float* __restrict__ be2,
    const float* __restrict__ W3, const float* __restrict__ b3, const float* __restrict__ g3, const float* __restrict__ be3,
    float* __restrict__ out)
{
    extern __shared__ float smem[];
    char*  smc  = reinterpret_cast<char*>(smem);
    float* sx   = smem + SX_F;          // [256][68] fp32 (stage 1)
    float* swf  = smem;                 // stage-1 weights overlay (in A_hi region)
    float* par2 = smem + PAR2_F;
    float* par3 = smem + PAR3_F;
    float* sred = smem + SRED_F;
    float* sfin = smem + SFIN_F;
    float* wmax = smem + WMAX_F;

    const uint32_t smb = smem_u32(smem);
    const int tid  = threadIdx.x;
    const int bm   = blockIdx.x;
    const int lane = tid & 31;
    const int w    = tid >> 5;

    // ======== STAGE 1 (scalar, stride 68) ========
    const int g1i = lane >> 3;          // node subgroup
    const int o8  = lane & 7;           // channel octant
    const int co  = 4 * o8;
    const int nb  = 16 * w + g1i;
    float* rows[4];
#pragma unroll
    for (int j = 0; j < 4; j++) rows[j] = sx + (nb + 4*j) * SXSTR;

    for (int i = tid; i < 512;  i += NTHREADS) swf[i]     = W0[i];
    if (tid < 64) { swf[512+tid]=b0[tid]; swf[576+tid]=g0[tid]; swf[640+tid]=be0[tid]; }
    for (int i = tid; i < 4096; i += NTHREADS) swf[704+i] = W1[i];
    if (tid >= 64 && tid < 128) {
        int i = tid - 64;
        swf[4800+i]=b1[i]; swf[4864+i]=g1[i]; swf[4928+i]=be1[i];
    }

    float x[4][8];
#pragma unroll
    for (int j = 0; j < 4; j++) {
        const float4* pa = reinterpret_cast<const float4*>(inp + ((size_t)bm * 256 + nb + 4*j) * 8);
        float4 a = pa[0], b = pa[1];
        x[j][0]=a.x; x[j][1]=a.y; x[j][2]=a.z; x[j][3]=a.w;
        x[j][4]=b.x; x[j][5]=b.y; x[j][6]=b.z; x[j][7]=b.w;
    }
    __syncthreads();

    // mlp0: 8 -> 64
    float h[4][8];
#pragma unroll
    for (int G = 0; G < 2; G++) {
        float4 b4 = *reinterpret_cast<const float4*>(&swf[512 + 32*G + co]);
#pragma unroll
        for (int j = 0; j < 4; j++) {
            h[j][4*G+0]=b4.x; h[j][4*G+1]=b4.y; h[j][4*G+2]=b4.z; h[j][4*G+3]=b4.w;
        }
    }
#pragma unroll
    for (int k = 0; k < 8; k++) {
#pragma unroll
        for (int G = 0; G < 2; G++) {
            float4 wv = *reinterpret_cast<const float4*>(&swf[k*64 + 32*G + co]);
#pragma unroll
            for (int j = 0; j < 4; j++) {
                float a = x[j][k];
                h[j][4*G+0] += a*wv.x; h[j][4*G+1] += a*wv.y;
                h[j][4*G+2] += a*wv.z; h[j][4*G+3] += a*wv.w;
            }
        }
    }
#pragma unroll
    for (int j = 0; j < 4; j++) {
        float sU = 0.f;
#pragma unroll
        for (int i = 0; i < 8; i++) sU += h[j][i];
        sU += __shfl_xor_sync(0xffffffffu, sU, 1);
        sU += __shfl_xor_sync(0xffffffffu, sU, 2);
        sU += __shfl_xor_sync(0xffffffffu, sU, 4);
        float mu = sU * (1.0f/64.0f), vv = 0.f;
#pragma unroll
        for (int i = 0; i < 8; i++) { float d = h[j][i]-mu; vv += d*d; }
        vv += __shfl_xor_sync(0xffffffffu, vv, 1);
        vv += __shfl_xor_sync(0xffffffffu, vv, 2);
        vv += __shfl_xor_sync(0xffffffffu, vv, 4);
        float rs = rsqrtf(vv * (1.0f/64.0f) + 1e-5f);
#pragma unroll
        for (int G = 0; G < 2; G++) {
            float4 g4  = *reinterpret_cast<const float4*>(&swf[576 + 32*G + co]);
            float4 be4 = *reinterpret_cast<const float4*>(&swf[640 + 32*G + co]);
            float4 r;
            r.x = fmaxf((h[j][4*G+0]-mu)*rs*g4.x + be4.x, 0.f);
            r.y = fmaxf((h[j][4*G+1]-mu)*rs*g4.y + be4.y, 0.f);
            r.z = fmaxf((h[j][4*G+2]-mu)*rs*g4.z + be4.z, 0.f);
            r.w = fmaxf((h[j][4*G+3]-mu)*rs*g4.w + be4.w, 0.f);
            *reinterpret_cast<float4*>(&rows[j][32*G + co]) = r;
        }
    }
    __syncwarp();

    // mlp1: 64 -> 64
    float e[4][8];
#pragma unroll
    for (int G = 0; G < 2; G++) {
        float4 b4 = *reinterpret_cast<const float4*>(&swf[4800 + 32*G + co]);
#pragma unroll
        for (int j = 0; j < 4; j++) {
            e[j][4*G+0]=b4.x; e[j][4*G+1]=b4.y; e[j][4*G+2]=b4.z; e[j][4*G+3]=b4.w;
        }
    }
    for (int k = 0; k < 64; k += 4) {
        float4 a4[4];
#pragma unroll
        for (int j = 0; j < 4; j++) a4[j] = *reinterpret_cast<const float4*>(&rows[j][k]);
        float av[4][4];
#pragma unroll
        for (int j = 0; j < 4; j++) { av[j][0]=a4[j].x; av[j][1]=a4[j].y; av[j][2]=a4[j].z; av[j][3]=a4[j].w; }
#pragma unroll
        for (int kk = 0; kk < 4; kk++) {
#pragma unroll
            for (int G = 0; G < 2; G++) {
                float4 wv = *reinterpret_cast<const float4*>(&swf[704 + (k+kk)*64 + 32*G + co]);
#pragma unroll
                for (int j = 0; j < 4; j++) {
                    float a = av[j][kk];
                    e[j][4*G+0] += a*wv.x; e[j][4*G+1] += a*wv.y;
                    e[j][4*G+2] += a*wv.z; e[j][4*G+3] += a*wv.w;
                }
            }
        }
    }
    __syncwarp();
#pragma unroll
    for (int j = 0; j < 4; j++) {
        float sU = 0.f;
#pragma unroll
        for (int i = 0; i < 8; i++) sU += e[j][i];
        sU += __shfl_xor_sync(0xffffffffu, sU, 1);
        sU += __shfl_xor_sync(0xffffffffu, sU, 2);
        sU += __shfl_xor_sync(0xffffffffu, sU, 4);
        float mu = sU * (1.0f/64.0f), vv = 0.f;
#pragma unroll
        for (int i = 0; i < 8; i++) { float d = e[j][i]-mu; vv += d*d; }
        vv += __shfl_xor_sync(0xffffffffu, vv, 1);
        vv += __shfl_xor_sync(0xffffffffu, vv, 2);
        vv += __shfl_xor_sync(0xffffffffu, vv, 4);
        float rs = rsqrtf(vv * (1.0f/64.0f) + 1e-5f);
#pragma unroll
        for (int G = 0; G < 2; G++) {
            float4 g4  = *reinterpret_cast<const float4*>(&swf[4864 + 32*G + co]);
            float4 be4 = *reinterpret_cast<const float4*>(&swf[4928 + 32*G + co]);
            float4 r;
            r.x = fmaxf((e[j][4*G+0]-mu)*rs*g4.x + be4.x, 0.f);
            r.y = fmaxf((e[j][4*G+1]-mu)*rs*g4.y + be4.y, 0.f);
            r.z = fmaxf((e[j][4*G+2]-mu)*rs*g4.z + be4.z, 0.f);
            r.w = fmaxf((e[j][4*G+3]-mu)*rs*g4.w + be4.w, 0.f);
            *reinterpret_cast<float4*>(&rows[j][32*G + co]) = r;
        }
    }
    __syncthreads();

    // top-2 + argmax per channel over 256 nodes
    {
        const int ch = tid & 63, chunk = tid >> 6;
        float m1 = -INFINITY, m2 = -INFINITY; int i1 = -1;
        const int jb = chunk * 32;
        for (int j = 0; j < 32; j++) {
            float v = sx[(jb + j) * SXSTR + ch];
            if (v > m1)      { m2 = m1; m1 = v; i1 = jb + j; }
            else if (v > m2) { m2 = v; }
        }
        sred[chunk * 64 + ch]       = m1;
        sred[512 + chunk * 64 + ch] = m2;
        reinterpret_cast<int*>(sred)[1024 + chunk * 64 + ch] = i1;
    }
    __syncthreads();
    if (tid < 64) {
        float m1 = sred[tid], m2 = sred[512 + tid];
        int   i1 = reinterpret_cast<int*>(sred)[1024 + tid];
#pragma unroll
        for (int c = 1; c < 8; c++) {
            float a1 = sred[c * 64 + tid], a2 = sred[512 + c * 64 + tid];
            int   ai = reinterpret_cast<int*>(sred)[1024 + c * 64 + tid];
            if (a1 > m1) { m2 = fmaxf(m1, a2); m1 = a1; i1 = ai; }
            else         { m2 = fmaxf(m2, a1); }
        }
        sfin[tid] = m1; sfin[64 + tid] = m2;
        reinterpret_cast<int*>(sfin)[128 + tid] = i1;
    }
    __syncthreads();

    // ======== concat -> A_hi/A_lo (bf16 split), thread = (row, half) ========
    {
        const int crow = tid >> 1, chalf = tid & 1;
        const float* sr = sx + crow * SXSTR;
        char* ah = smc + AH_B + crow * ASTR_B + chalf * 128;
        char* al = smc + AL_B + crow * ASTR_B + chalf * 128;
#pragma unroll
        for (int c = 0; c < 64; c += 2) {
            float v0, v1;
            if (chalf == 0) { v0 = sr[c]; v1 = sr[c+1]; }
            else {
                float a0 = sr[c], a1 = sr[c+1];
                int   j0 = reinterpret_cast<int*>(sfin)[128 + c];
                int   j1 = reinterpret_cast<int*>(sfin)[128 + c + 1];
                float e0x = (j0 == crow) ? sfin[64 + c]     : sfin[c];
                float e1x = (j1 == crow) ? sfin[64 + c + 1] : sfin[c + 1];
                v0 = fmaxf(e0x, a0 - 10000.0f);
                v1 = fmaxf(e1x, a1 - 10000.0f);
            }
            float h0 = bfr(v0);
            float h1 = bfr(v1);
            *reinterpret_cast<uint32_t*>(ah + c*2) = pack2(v0, v1);
            *reinterpret_cast<uint32_t*>(al + c*2) = pack2(v0 - h0, v1 - h1);
        }
    }
    __syncthreads();   // sx consumed; A buffers ready

    // ======== big layers: warp = (rb = w&7 node-block, cg = w>>3 col-group) ========
    const int rb = w & 7, cg = w >> 3, ob = cg * 64;
    const int lg = lane >> 3, lr = lane & 7;
    const int tq = lane & 3, tr = lane >> 2;   // quad col, row-in-tile
    // A: [m][k] row-major, non-trans ldmatrix (rows 16B-aligned: 272%16==0)
    const uint32_t aoff = smb + AH_B + (uint32_t)(rb*32 + ((lg&1)<<3) + lr) * ASTR_B + ((lg>>1)<<4);
    // B: W stored K-MAJOR [k][o]; trans ldmatrix. matrix0/1 = k0-7/k8-15 of o-grp0,
    // matrix2/3 = same for o-grp1 -> lane mapping: row k = (lg&1)*8 + lr, o-byte = (lg>>1)*16.
    const uint32_t boff = smb + WH_B + (uint32_t)(((lg&1)<<3) + lr) * ASTR_B + (uint32_t)(ob*2 + ((lg>>1)<<4));
    float* psumS = sred;          // [512]
    float* psumQ = sred + 512;    // [512]

    float acc[2][8][4];

    for (int layer = 0; layer < 2; layer++) {
        const float* par = layer ? par3 : par2;
        // ---- W -> smem bf16 hi/lo, K-MAJOR (straight vectorized copy) ----
        {
            const float4* Wg4 = reinterpret_cast<const float4*>(layer ? W3 : W2);
            for (int i = tid; i < 4096; i += NTHREADS) {   // 8 iters/thread
                int k = i >> 5, o4 = i & 31;               // 32 float4 per k-row
                float4 v = Wg4[i];
                uint32_t off = (uint32_t)k * ASTR_B + o4 * 8;
                uint2 hi2 = make_uint2(pack2(v.x, v.y), pack2(v.z, v.w));
                uint2 lo2 = make_uint2(pack2(v.x - bfr(v.x), v.y - bfr(v.y)),
                                       pack2(v.z - bfr(v.z), v.w - bfr(v.w)));
                *reinterpret_cast<uint2*>(smc + WH_B + off) = hi2;
                *reinterpret_cast<uint2*>(smc + WL_B + off) = lo2;
            }
            if (tid < 128) {
                float* pdst = layer ? par3 : par2;
                pdst[tid]       = layer ? b3[tid]  : b2[tid];
                pdst[128 + tid] = layer ? g3[tid]  : g2[tid];
                pdst[256 + tid] = layer ? be3[tid] : be2[tid];
            }
        }
        __syncthreads();

        // ---- MMA: C[32 nodes][64 outs] via split-bf16 (hi*hi + hi*lo + lo*hi) ----
#pragma unroll
        for (int mt = 0; mt < 2; mt++)
#pragma unroll
            for (int nt = 0; nt < 8; nt++)
#pragma unroll
                for (int q = 0; q < 4; q++) acc[mt][nt][q] = 0.f;

        for (int ks = 0; ks < 8; ks++) {
            const uint32_t kb  = (uint32_t)ks * 32;              // A: 16 bf16 along k
            const uint32_t kbw = (uint32_t)ks * 16 * ASTR_B;     // B: 16 k-rows
            uint32_t Ah[2][4], Al[2][4];
            ldm4(Ah[0][0], Ah[0][1], Ah[0][2], Ah[0][3], aoff + kb);
            ldm4(Ah[1][0], Ah[1][1], Ah[1][2], Ah[1][3], aoff + 16*ASTR_B + kb);
            ldm4(Al[0][0], Al[0][1], Al[0][2], Al[0][3], aoff + (AL_B - AH_B) + kb);
            ldm4(Al[1][0], Al[1][1], Al[1][2], Al[1][3], aoff + (AL_B - AH_B) + 16*ASTR_B + kb);
#pragma unroll
            for (int p = 0; p < 4; p++) {
                uint32_t Bh[4], Bl[4];
                ldm4t(Bh[0], Bh[1], Bh[2], Bh[3], boff + kbw + (uint32_t)p*32);
                ldm4t(Bl[0], Bl[1], Bl[2], Bl[3], boff + (WL_B - WH_B) + kbw + (uint32_t)p*32);
#pragma unroll
                for (int mt = 0; mt < 2; mt++) {
                    mma16816(acc[mt][2*p],   Ah[mt], Bh);
                    mma16816(acc[mt][2*p],   Ah[mt], Bl);
                    mma16816(acc[mt][2*p],   Al[mt], Bh);
                    mma16816(acc[mt][2*p+1], Ah[mt], Bh + 2);
                    mma16816(acc[mt][2*p+1], Ah[mt], Bl + 2);
                    mma16816(acc[mt][2*p+1], Al[mt], Bh + 2);
                }
            }
        }

        // ---- epilogue: bias, LN partial sums (per node, per col-group) ----
        float rS[2][2] = {{0.f,0.f},{0.f,0.f}}, rQ[2][2] = {{0.f,0.f},{0.f,0.f}};
#pragma unroll
        for (int mt = 0; mt < 2; mt++) {
#pragma unroll
            for (int nt = 0; nt < 8; nt++) {
                int col0 = ob + nt*8 + 2*tq;
                float2 bb = *reinterpret_cast<const float2*>(&par[col0]);
                float v00 = acc[mt][nt][0] + bb.x, v01 = acc[mt][nt][1] + bb.y;
                float v10 = acc[mt][nt][2] + bb.x, v11 = acc[mt][nt][3] + bb.y;
                acc[mt][nt][0]=v00; acc[mt][nt][1]=v01; acc[mt][nt][2]=v10; acc[mt][nt][3]=v11;
                rS[mt][0]+=v00+v01; rS[mt][1]+=v10+v11;
                rQ[mt][0]+=v00*v00+v01*v01; rQ[mt][1]+=v10*v10+v11*v11;
            }
        }
#pragma unroll
        for (int mt = 0; mt < 2; mt++)
#pragma unroll
            for (int rh = 0; rh < 2; rh++) {
                rS[mt][rh] += __shfl_xor_sync(0xffffffffu, rS[mt][rh], 1);
                rS[mt][rh] += __shfl_xor_sync(0xffffffffu, rS[mt][rh], 2);
                rQ[mt][rh] += __shfl_xor_sync(0xffffffffu, rQ[mt][rh], 1);
                rQ[mt][rh] += __shfl_xor_sync(0xffffffffu, rQ[mt][rh], 2);
            }
        if (tq == 0) {
#pragma unroll
            for (int mt = 0; mt < 2; mt++)
#pragma unroll
                for (int rh = 0; rh < 2; rh++) {
                    int node = rb*32 + mt*16 + rh*8 + tr;
                    psumS[node*2 + cg] = rS[mt][rh];
                    psumQ[node*2 + cg] = rQ[mt][rh];
                }
        }
        __syncthreads();

        float muv[2][2], rsv[2][2];
#pragma unroll
        for (int mt = 0; mt < 2; mt++)
#pragma unroll
            for (int rh = 0; rh < 2; rh++) {
                int node = rb*32 + mt*16 + rh*8 + tr;
                float S = psumS[node*2] + psumS[node*2+1];
                float Q = psumQ[node*2] + psumQ[node*2+1];
                float mu = S * (1.0f/128.0f);
                muv[mt][rh] = mu;
                rsv[mt][rh] = rsqrtf(Q * (1.0f/128.0f) - mu*mu + 1e-5f);
            }

        if (layer == 0) {
            // normalize + ReLU, write as next-layer A (bf16 hi/lo)
#pragma unroll
            for (int mt = 0; mt < 2; mt++) {
#pragma unroll
                for (int nt = 0; nt < 8; nt++) {
                    int col0 = ob + nt*8 + 2*tq;
                    float2 gg = *reinterpret_cast<const float2*>(&par[128 + col0]);
                    float2 bb = *reinterpret_cast<const float2*>(&par[256 + col0]);
                    int row0 = rb*32 + mt*16 + tr;
                    float v00 = fmaxf((acc[mt][nt][0]-muv[mt][0])*rsv[mt][0]*gg.x + bb.x, 0.f);
                    float v01 = fmaxf((acc[mt][nt][1]-muv[mt][0])*rsv[mt][0]*gg.y + bb.y, 0.f);
                    float v10 = fmaxf((acc[mt][nt][2]-muv[mt][1])*rsv[mt][1]*gg.x + bb.x, 0.f);
                    float v11 = fmaxf((acc[mt][nt][3]-muv[mt][1])*rsv[mt][1]*gg.y + bb.y, 0.f);
                    uint32_t off0 = (uint32_t)row0 * ASTR_B + col0*2;
                    uint32_t off1 = off0 + 8*ASTR_B;
                    *reinterpret_cast<uint32_t*>(smc + AH_B + off0) = pack2(v00, v01);
                    *reinterpret_cast<uint32_t*>(smc + AH_B + off1) = pack2(v10, v11);
                    *reinterpret_cast<uint32_t*>(smc + AL_B + off0) = pack2(v00 - bfr(v00), v01 - bfr(v01));
                    *reinterpret_cast<uint32_t*>(smc + AL_B + off1) = pack2(v10 - bfr(v10), v11 - bfr(v11));
                }
            }
            __syncthreads();   // A ready; W2 reads done -> W3 load next iter
        } else {
            // normalize + ReLU, column max over warp's 32 nodes
            float cm[8][2];
#pragma unroll
            for (int nt = 0; nt < 8; nt++) { cm[nt][0] = -INFINITY; cm[nt][1] = -INFINITY; }
#pragma unroll
            for (int mt = 0; mt < 2; mt++) {
#pragma unroll
                for (int nt = 0; nt < 8; nt++) {
                    int col0 = ob + nt*8 + 2*tq;
                    float2 gg = *reinterpret_cast<const float2*>(&par[128 + col0]);
                    float2 bb = *reinterpret_cast<const float2*>(&par[256 + col0]);
                    float v00 = fmaxf((acc[mt][nt][0]-muv[mt][0])*rsv[mt][0]*gg.x + bb.x, 0.f);
                    float v01 = fmaxf((acc[mt][nt][1]-muv[mt][0])*rsv[mt][0]*gg.y + bb.y, 0.f);
                    float v10 = fmaxf((acc[mt][nt][2]-muv[mt][1])*rsv[mt][1]*gg.x + bb.x, 0.f);
                    float v11 = fmaxf((acc[mt][nt][3]-muv[mt][1])*rsv[mt][1]*gg.y + bb.y, 0.f);
                    cm[nt][0] = fmaxf(cm[nt][0], fmaxf(v00, v10));
                    cm[nt][1] = fmaxf(cm[nt][1], fmaxf(v01, v11));
                }
            }
#pragma unroll
            for (int nt = 0; nt < 8; nt++)
#pragma unroll
                for (int q = 0; q < 2; q++) {
                    cm[nt][q] = fmaxf(cm[nt][q], __shfl_xor_sync(0xffffffffu, cm[nt][q], 4));
                    cm[nt][q] = fmaxf(cm[nt][q], __shfl_xor_sync(0xffffffffu, cm[nt][q], 8));
                    cm[nt][q] = fmaxf(cm[nt][q], __shfl_xor_sync(0xffffffffu, cm[nt][q], 16));
                }
            if (tr == 0) {
#pragma unroll
                for (int nt = 0; nt < 8; nt++) {
                    wmax[w*64 + nt*8 + 2*tq]     = cm[nt][0];
                    wmax[w*64 + nt*8 + 2*tq + 1] = cm[nt][1];
                }
            }
        }
    }
    __syncthreads();

    // ---- final reduce: out[d] = out[128+d] = max over 8 node-block warps ----
    if (tid < 128) {
        int cgd = tid >> 6, dd = tid & 63;
        float m = -INFINITY;
#pragma unroll
        for (int i = 0; i < 8; i++) m = fmaxf(m, wmax[(cgd*8 + i)*64 + dd]);
        out[(size_t)bm * 256 + cgd*64 + dd]       = m;
        out[(size_t)bm * 256 + 128 + cgd*64 + dd] = m;
    }
}

extern "C" void kernel_launch(void* const* d_in, const int* in_sizes, int n_in,
                              void* d_out, int out_size)
{
    const int INPUT_ELEMS = 8 * 128 * 256 * 8;   // 2,097,152
    const float* inp = nullptr;
    const float* wt[16];
    int wi = 0;
    for (int i = 0; i < n_in; i++) {
        if (in_sizes[i] == INPUT_ELEMS) inp = (const float*)d_in[i];
        else if (wi < 16)               wt[wi++] = (const float*)d_in[i];
    }

    cudaFuncSetAttribute(localgraph_fused_kernel,
                         cudaFuncAttributeMaxDynamicSharedMemorySize, SMEM_BYTES);

    localgraph_fused_kernel<<<8 * 128, NTHREADS, SMEM_BYTES>>>(
        inp,
        wt[0],  wt[1],  wt[2],  wt[3],
        wt[4],  wt[5],  wt[6],  wt[7],
        wt[8],  wt[9],  wt[10], wt[11],
        wt[12], wt[13], wt[14], wt[15],
        (float*)d_out);
}

// round 13
// speedup vs baseline: 5.2963x; 1.1777x over previous
#include <cuda_runtime.h>
#include <cuda_bf16.h>
#include <math.h>
#include <stdint.h>

#define NTHREADS 512
#define SXSTR 68            // fp32 row stride (floats)
#define ASTR_B 272          // bf16 row stride in BYTES (136 bf16; 272%16==0 for ldmatrix)

// ---- byte offsets ----
#define AH_B 0              // A_hi  [256][136] bf16 = 69632 B
#define AL_B 69632          // A_lo
#define WH_B 139264         // W_hi  [128 k-rows][136 bf16] = 34816 B (K-MAJOR); W1_hi rows 0..63 in stage 1
#define WL_B 174080         // W_lo  (ends 208896);                     W1_lo rows 0..63 in stage 1
// ---- float offsets ----
#define SX_F   34816        // fp32 [256][68] overlay on W region (written AFTER W1 reads complete)
#define PAR2_F 52224        // b2|g2|be2 (384 floats)
#define PAR3_F 52608        // b3|g3|be3
#define SRED_F 52992        // 1536: top2 partials / LN psums; pstg (896) aliases this in stage 1
#define SFIN_F 54528        // 192: final top-2 per channel
#define WMAX_F 54720        // 1024: per-warp column maxima
#define SMEM_FLOATS 55744
#define SMEM_BYTES (SMEM_FLOATS*4)   // 222976 — identical to the passing R10 kernel

__device__ __forceinline__ uint32_t smem_u32(const void* p) {
    uint32_t a;
    asm("{ .reg .u64 t; cvta.to.shared.u64 t, %1; cvt.u32.u64 %0, t; }" : "=r"(a) : "l"(p));
    return a;
}
__device__ __forceinline__ void ldm4(uint32_t& r0, uint32_t& r1, uint32_t& r2, uint32_t& r3, uint32_t a) {
    asm volatile("ldmatrix.sync.aligned.m8n8.x4.shared.b16 {%0,%1,%2,%3}, [%4];"
                 : "=r"(r0), "=r"(r1), "=r"(r2), "=r"(r3) : "r"(a));
}
__device__ __forceinline__ void ldm4t(uint32_t& r0, uint32_t& r1, uint32_t& r2, uint32_t& r3, uint32_t a) {
    asm volatile("ldmatrix.sync.aligned.m8n8.x4.trans.shared.b16 {%0,%1,%2,%3}, [%4];"
                 : "=r"(r0), "=r"(r1), "=r"(r2), "=r"(r3) : "r"(a));
}
__device__ __forceinline__ void mma16816(float* c, const uint32_t* A, const uint32_t* B) {
    asm volatile("mma.sync.aligned.m16n8k16.row.col.f32.bf16.bf16.f32 "
                 "{%0,%1,%2,%3},{%4,%5,%6,%7},{%8,%9},{%0,%1,%2,%3};"
                 : "+f"(c[0]), "+f"(c[1]), "+f"(c[2]), "+f"(c[3])
                 : "r"(A[0]), "r"(A[1]), "r"(A[2]), "r"(A[3]), "r"(B[0]), "r"(B[1]));
}
__device__ __forceinline__ uint32_t pack2(float a, float b) {
    __nv_bfloat162 t = __floats2bfloat162_rn(a, b);
    uint32_t r; memcpy(&r, &t, 4); return r;
}
__device__ __forceinline__ float bfr(float v) {
    return __bfloat162float(__float2bfloat16(v));
}

__global__ __launch_bounds__(NTHREADS, 1)
void localgraph_fused_kernel(
    const float* __restrict__ inp,
    const float* __restrict__ W0, const float* __restrict__ b0, const float* __restrict__ g0, const float* __restrict__ be0,
    const float* __restrict__ W1, const float* __restrict__ b1, const float* __restrict__ g1, const float* __restrict__ be1,
    const float* __restrict__ W2, const float* __restrict__ b2, const float* __restrict__ g2, const float* __restrict__ be2,
    const float* __restrict__ W3, const float* __restrict__ b3, const float* __restrict__ g3, const float* __restrict__ be3,
    float* __restrict__ out)
{
    extern __shared__ float smem[];
    char*  smc  = reinterpret_cast<char*>(smem);
    float* sx   = smem + SX_F;          // [256][68] fp32
    float* pstg = smem + SRED_F;        // stage-1 weights/params (aliases sred; dead before top-2)
    float* par2 = smem + PAR2_F;
    float* par3 = smem + PAR3_F;
    float* sred = smem + SRED_F;
    float* sfin = smem + SFIN_F;
    float* wmax = smem + WMAX_F;

    const uint32_t smb = smem_u32(smem);
    const int tid  = threadIdx.x;
    const int bm   = blockIdx.x;
    const int lane = tid & 31;
    const int w    = tid >> 5;
    const int lg = lane >> 3, lr = lane & 7;
    const int tq = lane & 3, tr = lane >> 2;

    // ======== STAGE 1 staging ========
    // W0 fp32 + params -> pstg; W1 -> bf16 hi/lo K-major at WH_B/WL_B (rows 0..63)
    for (int i = tid; i < 512; i += NTHREADS) pstg[i] = W0[i];
    if (tid < 64) { pstg[512+tid]=b0[tid]; pstg[576+tid]=g0[tid]; pstg[640+tid]=be0[tid]; }
    if (tid >= 64 && tid < 128) {
        int i = tid - 64;
        pstg[704+i]=b1[i]; pstg[768+i]=g1[i]; pstg[832+i]=be1[i];
    }
    {   // W1 [k=64][o=64]: 1024 float4, straight vectorized copy
        const float4* W1g = reinterpret_cast<const float4*>(W1);
        for (int i = tid; i < 1024; i += NTHREADS) {   // 2 iters/thread
            int k = i >> 4, o4 = i & 15;               // 16 float4 per k-row
            float4 v = W1g[i];
            uint32_t off = (uint32_t)k * ASTR_B + o4 * 8;
            *reinterpret_cast<uint2*>(smc + WH_B + off) =
                make_uint2(pack2(v.x, v.y), pack2(v.z, v.w));
            *reinterpret_cast<uint2*>(smc + WL_B + off) =
                make_uint2(pack2(v.x - bfr(v.x), v.y - bfr(v.y)),
                           pack2(v.z - bfr(v.z), v.w - bfr(v.w)));
        }
    }

    // stage-1 scalar decomposition: warp w owns nodes 16w..16w+15
    const int sg  = lane >> 3;          // node subgroup 0..3
    const int so8 = lane & 7;           // channel octant 0..7
    const int sco = 4 * so8;
    const int nb  = 16 * w + sg;        // thread's nodes: nb + 4j

    float x[4][8];
#pragma unroll
    for (int j = 0; j < 4; j++) {
        const float4* pa = reinterpret_cast<const float4*>(inp + ((size_t)bm * 256 + nb + 4*j) * 8);
        float4 a = pa[0], b = pa[1];
        x[j][0]=a.x; x[j][1]=a.y; x[j][2]=a.z; x[j][3]=a.w;
        x[j][4]=b.x; x[j][5]=b.y; x[j][6]=b.z; x[j][7]=b.w;
    }
    __syncthreads();

    // ---- mlp0 (scalar): 8 -> 64, LN, ReLU -> bf16 A hi/lo cols 0..63 ----
    {
        float h[4][8];
#pragma unroll
        for (int G = 0; G < 2; G++) {
            float4 b4 = *reinterpret_cast<const float4*>(&pstg[512 + 32*G + sco]);
#pragma unroll
            for (int j = 0; j < 4; j++) {
                h[j][4*G+0]=b4.x; h[j][4*G+1]=b4.y; h[j][4*G+2]=b4.z; h[j][4*G+3]=b4.w;
            }
        }
#pragma unroll
        for (int k = 0; k < 8; k++) {
#pragma unroll
            for (int G = 0; G < 2; G++) {
                float4 wv = *reinterpret_cast<const float4*>(&pstg[k*64 + 32*G + sco]);
#pragma unroll
                for (int j = 0; j < 4; j++) {
                    float a = x[j][k];
                    h[j][4*G+0] += a*wv.x; h[j][4*G+1] += a*wv.y;
                    h[j][4*G+2] += a*wv.z; h[j][4*G+3] += a*wv.w;
                }
            }
        }
#pragma unroll
        for (int j = 0; j < 4; j++) {
            float sU = 0.f;
#pragma unroll
            for (int i = 0; i < 8; i++) sU += h[j][i];
            sU += __shfl_xor_sync(0xffffffffu, sU, 1);
            sU += __shfl_xor_sync(0xffffffffu, sU, 2);
            sU += __shfl_xor_sync(0xffffffffu, sU, 4);
            float mu = sU * (1.0f/64.0f), vv = 0.f;
#pragma unroll
            for (int i = 0; i < 8; i++) { float d = h[j][i]-mu; vv += d*d; }
            vv += __shfl_xor_sync(0xffffffffu, vv, 1);
            vv += __shfl_xor_sync(0xffffffffu, vv, 2);
            vv += __shfl_xor_sync(0xffffffffu, vv, 4);
            float rs = rsqrtf(vv * (1.0f/64.0f) + 1e-5f);
            uint32_t rowoff = (uint32_t)(nb + 4*j) * ASTR_B;
#pragma unroll
            for (int G = 0; G < 2; G++) {
                float4 g4  = *reinterpret_cast<const float4*>(&pstg[576 + 32*G + sco]);
                float4 be4 = *reinterpret_cast<const float4*>(&pstg[640 + 32*G + sco]);
                float v0 = fmaxf((h[j][4*G+0]-mu)*rs*g4.x + be4.x, 0.f);
                float v1 = fmaxf((h[j][4*G+1]-mu)*rs*g4.y + be4.y, 0.f);
                float v2 = fmaxf((h[j][4*G+2]-mu)*rs*g4.z + be4.z, 0.f);
                float v3 = fmaxf((h[j][4*G+3]-mu)*rs*g4.w + be4.w, 0.f);
                uint32_t off = rowoff + (32*G + sco) * 2;
                *reinterpret_cast<uint2*>(smc + AH_B + off) =
                    make_uint2(pack2(v0, v1), pack2(v2, v3));
                *reinterpret_cast<uint2*>(smc + AL_B + off) =
                    make_uint2(pack2(v0 - bfr(v0), v1 - bfr(v1)),
                               pack2(v2 - bfr(v2), v3 - bfr(v3)));
            }
        }
    }
    __syncthreads();   // A cols 0..63 + W1 visible to all

    // ---- mlp1 (tensor): 64 -> 64, split-bf16; warp owns 16 nodes x 64 cols ----
    {
        const uint32_t aoff1 = smb + AH_B + (uint32_t)(16*w + ((lg&1)<<3) + lr) * ASTR_B + ((lg>>1)<<4);
        const uint32_t boff1 = smb + WH_B + (uint32_t)(((lg&1)<<3) + lr) * ASTR_B + ((lg>>1)<<4);
        float acc1[8][4];
#pragma unroll
        for (int nt = 0; nt < 8; nt++)
#pragma unroll
            for (int q = 0; q < 4; q++) acc1[nt][q] = 0.f;

#pragma unroll
        for (int ks = 0; ks < 4; ks++) {
            const uint32_t kb  = (uint32_t)ks * 32;
            const uint32_t kbw = (uint32_t)ks * 16 * ASTR_B;
            uint32_t Ah[4], Al[4];
            ldm4(Ah[0], Ah[1], Ah[2], Ah[3], aoff1 + kb);
            ldm4(Al[0], Al[1], Al[2], Al[3], aoff1 + (AL_B - AH_B) + kb);
#pragma unroll
            for (int p = 0; p < 4; p++) {
                uint32_t Bh[4], Bl[4];
                ldm4t(Bh[0], Bh[1], Bh[2], Bh[3], boff1 + kbw + (uint32_t)p*32);
                ldm4t(Bl[0], Bl[1], Bl[2], Bl[3], boff1 + (WL_B - WH_B) + kbw + (uint32_t)p*32);
                mma16816(acc1[2*p],   Ah, Bh);
                mma16816(acc1[2*p],   Ah, Bl);
                mma16816(acc1[2*p],   Al, Bh);
                mma16816(acc1[2*p+1], Ah, Bh + 2);
                mma16816(acc1[2*p+1], Ah, Bl + 2);
                mma16816(acc1[2*p+1], Al, Bh + 2);
            }
        }
        __syncthreads();   // ALL warps done reading W1 before sx (overlapping region) is written

        // epilogue: bias + LN (warp-local rows) + ReLU -> fp32 sx AND bf16 A
        float rS[2] = {0.f, 0.f}, rQ[2] = {0.f, 0.f};
#pragma unroll
        for (int nt = 0; nt < 8; nt++) {
            int col0 = nt*8 + 2*tq;
            float2 bb = *reinterpret_cast<const float2*>(&pstg[704 + col0]);
            float v00 = acc1[nt][0] + bb.x, v01 = acc1[nt][1] + bb.y;
            float v10 = acc1[nt][2] + bb.x, v11 = acc1[nt][3] + bb.y;
            acc1[nt][0]=v00; acc1[nt][1]=v01; acc1[nt][2]=v10; acc1[nt][3]=v11;
            rS[0]+=v00+v01; rS[1]+=v10+v11;
            rQ[0]+=v00*v00+v01*v01; rQ[1]+=v10*v10+v11*v11;
        }
#pragma unroll
        for (int rh = 0; rh < 2; rh++) {
            rS[rh] += __shfl_xor_sync(0xffffffffu, rS[rh], 1);
            rS[rh] += __shfl_xor_sync(0xffffffffu, rS[rh], 2);
            rQ[rh] += __shfl_xor_sync(0xffffffffu, rQ[rh], 1);
            rQ[rh] += __shfl_xor_sync(0xffffffffu, rQ[rh], 2);
        }
        float muv[2], rsv[2];
#pragma unroll
        for (int rh = 0; rh < 2; rh++) {
            float mu = rS[rh] * (1.0f/64.0f);
            muv[rh] = mu;
            rsv[rh] = rsqrtf(rQ[rh] * (1.0f/64.0f) - mu*mu + 1e-5f);
        }
        int node0 = 16*w + tr, node1 = node0 + 8;
#pragma unroll
        for (int nt = 0; nt < 8; nt++) {
            int col0 = nt*8 + 2*tq;
            float2 gg = *reinterpret_cast<const float2*>(&pstg[768 + col0]);
            float2 bb = *reinterpret_cast<const float2*>(&pstg[832 + col0]);
            float v00 = fmaxf((acc1[nt][0]-muv[0])*rsv[0]*gg.x + bb.x, 0.f);
            float v01 = fmaxf((acc1[nt][1]-muv[0])*rsv[0]*gg.y + bb.y, 0.f);
            float v10 = fmaxf((acc1[nt][2]-muv[1])*rsv[1]*gg.x + bb.x, 0.f);
            float v11 = fmaxf((acc1[nt][3]-muv[1])*rsv[1]*gg.y + bb.y, 0.f);
            *reinterpret_cast<float2*>(&sx[node0*SXSTR + col0]) = make_float2(v00, v01);
            *reinterpret_cast<float2*>(&sx[node1*SXSTR + col0]) = make_float2(v10, v11);
            uint32_t off0 = (uint32_t)node0 * ASTR_B + col0*2;
            uint32_t off1 = (uint32_t)node1 * ASTR_B + col0*2;
            *reinterpret_cast<uint32_t*>(smc + AH_B + off0) = pack2(v00, v01);
            *reinterpret_cast<uint32_t*>(smc + AH_B + off1) = pack2(v10, v11);
            *reinterpret_cast<uint32_t*>(smc + AL_B + off0) = pack2(v00 - bfr(v00), v01 - bfr(v01));
            *reinterpret_cast<uint32_t*>(smc + AL_B + off1) = pack2(v10 - bfr(v10), v11 - bfr(v11));
        }
    }
    __syncthreads();

    // ---- top-2 + argmax per channel over 256 nodes (reads fp32 sx) ----
    {
        const int ch = tid & 63, chunk = tid >> 6;
        float m1 = -INFINITY, m2 = -INFINITY; int i1 = -1;
        const int jb = chunk * 32;
        for (int j = 0; j < 32; j++) {
            float v = sx[(jb + j) * SXSTR + ch];
            if (v > m1)      { m2 = m1; m1 = v; i1 = jb + j; }
            else if (v > m2) { m2 = v; }
        }
        sred[chunk * 64 + ch]       = m1;
        sred[512 + chunk * 64 + ch] = m2;
        reinterpret_cast<int*>(sred)[1024 + chunk * 64 + ch] = i1;
    }
    __syncthreads();
    if (tid < 64) {
        float m1 = sred[tid], m2 = sred[512 + tid];
        int   i1 = reinterpret_cast<int*>(sred)[1024 + tid];
#pragma unroll
        for (int c = 1; c < 8; c++) {
            float a1 = sred[c * 64 + tid], a2 = sred[512 + c * 64 + tid];
            int   ai = reinterpret_cast<int*>(sred)[1024 + c * 64 + tid];
            if (a1 > m1) { m2 = fmaxf(m1, a2); m1 = a1; i1 = ai; }
            else         { m2 = fmaxf(m2, a1); }
        }
        sfin[tid] = m1; sfin[64 + tid] = m2;
        reinterpret_cast<int*>(sfin)[128 + tid] = i1;
    }
    __syncthreads();

    // ---- concat (excl half only): A cols 64..127 ----
    {
        const int crow = tid >> 1, chalf = tid & 1;
        const float* sr = sx + crow * SXSTR;
        const int cb = chalf * 32;     // source channel base 0 or 32
        char* ah = smc + AH_B + crow * ASTR_B + (64 + cb) * 2;
        char* al = smc + AL_B + crow * ASTR_B + (64 + cb) * 2;
#pragma unroll
        for (int c = 0; c < 32; c += 2) {
            int d = cb + c;
            float a0 = sr[d], a1 = sr[d+1];
            int   j0 = reinterpret_cast<int*>(sfin)[128 + d];
            int   j1 = reinterpret_cast<int*>(sfin)[128 + d + 1];
            float e0x = (j0 == crow) ? sfin[64 + d]     : sfin[d];
            float e1x = (j1 == crow) ? sfin[64 + d + 1] : sfin[d + 1];
            float v0 = fmaxf(e0x, a0 - 10000.0f);
            float v1 = fmaxf(e1x, a1 - 10000.0f);
            *reinterpret_cast<uint32_t*>(ah + c*2) = pack2(v0, v1);
            *reinterpret_cast<uint32_t*>(al + c*2) = pack2(v0 - bfr(v0), v1 - bfr(v1));
        }
    }
    __syncthreads();   // sx consumed; full A ready

    // ======== big layers: warp = (rb = w&7 node-block, cg = w>>3 col-group) ========
    const int rb = w & 7, cg = w >> 3, ob = cg * 64;
    const uint32_t aoff = smb + AH_B + (uint32_t)(rb*32 + ((lg&1)<<3) + lr) * ASTR_B + ((lg>>1)<<4);
    const uint32_t boff = smb + WH_B + (uint32_t)(((lg&1)<<3) + lr) * ASTR_B + (uint32_t)(ob*2 + ((lg>>1)<<4));
    float* psumS = sred;          // [512]
    float* psumQ = sred + 512;    // [512]

    float acc[2][8][4];

    for (int layer = 0; layer < 2; layer++) {
        const float* par = layer ? par3 : par2;
        // ---- W -> smem bf16 hi/lo, K-MAJOR (straight vectorized copy) ----
        {
            const float4* Wg4 = reinterpret_cast<const float4*>(layer ? W3 : W2);
            for (int i = tid; i < 4096; i += NTHREADS) {   // 8 iters/thread
                int k = i >> 5, o4 = i & 31;
                float4 v = Wg4[i];
                uint32_t off = (uint32_t)k * ASTR_B + o4 * 8;
                *reinterpret_cast<uint2*>(smc + WH_B + off) =
                    make_uint2(pack2(v.x, v.y), pack2(v.z, v.w));
                *reinterpret_cast<uint2*>(smc + WL_B + off) =
                    make_uint2(pack2(v.x - bfr(v.x), v.y - bfr(v.y)),
                               pack2(v.z - bfr(v.z), v.w - bfr(v.w)));
            }
            if (tid < 128) {
                float* pdst = layer ? par3 : par2;
                pdst[tid]       = layer ? b3[tid]  : b2[tid];
                pdst[128 + tid] = layer ? g3[tid]  : g2[tid];
                pdst[256 + tid] = layer ? be3[tid] : be2[tid];
            }
        }
        __syncthreads();

        // ---- MMA: C[32 nodes][64 outs] via split-bf16 ----
#pragma unroll
        for (int mt = 0; mt < 2; mt++)
#pragma unroll
            for (int nt = 0; nt < 8; nt++)
#pragma unroll
                for (int q = 0; q < 4; q++) acc[mt][nt][q] = 0.f;

        for (int ks = 0; ks < 8; ks++) {
            const uint32_t kb  = (uint32_t)ks * 32;
            const uint32_t kbw = (uint32_t)ks * 16 * ASTR_B;
            uint32_t Ah[2][4], Al[2][4];
            ldm4(Ah[0][0], Ah[0][1], Ah[0][2], Ah[0][3], aoff + kb);
            ldm4(Ah[1][0], Ah[1][1], Ah[1][2], Ah[1][3], aoff + 16*ASTR_B + kb);
            ldm4(Al[0][0], Al[0][1], Al[0][2], Al[0][3], aoff + (AL_B - AH_B) + kb);
            ldm4(Al[1][0], Al[1][1], Al[1][2], Al[1][3], aoff + (AL_B - AH_B) + 16*ASTR_B + kb);
#pragma unroll
            for (int p = 0; p < 4; p++) {
                uint32_t Bh[4], Bl[4];
                ldm4t(Bh[0], Bh[1], Bh[2], Bh[3], boff + kbw + (uint32_t)p*32);
                ldm4t(Bl[0], Bl[1], Bl[2], Bl[3], boff + (WL_B - WH_B) + kbw + (uint32_t)p*32);
#pragma unroll
                for (int mt = 0; mt < 2; mt++) {
                    mma16816(acc[mt][2*p],   Ah[mt], Bh);
                    mma16816(acc[mt][2*p],   Ah[mt], Bl);
                    mma16816(acc[mt][2*p],   Al[mt], Bh);
                    mma16816(acc[mt][2*p+1], Ah[mt], Bh + 2);
                    mma16816(acc[mt][2*p+1], Ah[mt], Bl + 2);
                    mma16816(acc[mt][2*p+1], Al[mt], Bh + 2);
                }
            }
        }

        // ---- epilogue: bias, LN partial sums ----
        float rS[2][2] = {{0.f,0.f},{0.f,0.f}}, rQ[2][2] = {{0.f,0.f},{0.f,0.f}};
#pragma unroll
        for (int mt = 0; mt < 2; mt++) {
#pragma unroll
            for (int nt = 0; nt < 8; nt++) {
                int col0 = ob + nt*8 + 2*tq;
                float2 bb = *reinterpret_cast<const float2*>(&par[col0]);
                float v00 = acc[mt][nt][0] + bb.x, v01 = acc[mt][nt][1] + bb.y;
                float v10 = acc[mt][nt][2] + bb.x, v11 = acc[mt][nt][3] + bb.y;
                acc[mt][nt][0]=v00; acc[mt][nt][1]=v01; acc[mt][nt][2]=v10; acc[mt][nt][3]=v11;
                rS[mt][0]+=v00+v01; rS[mt][1]+=v10+v11;
                rQ[mt][0]+=v00*v00+v01*v01; rQ[mt][1]+=v10*v10+v11*v11;
            }
        }
#pragma unroll
        for (int mt = 0; mt < 2; mt++)
#pragma unroll
            for (int rh = 0; rh < 2; rh++) {
                rS[mt][rh] += __shfl_xor_sync(0xffffffffu, rS[mt][rh], 1);
                rS[mt][rh] += __shfl_xor_sync(0xffffffffu, rS[mt][rh], 2);
                rQ[mt][rh] += __shfl_xor_sync(0xffffffffu, rQ[mt][rh], 1);
                rQ[mt][rh] += __shfl_xor_sync(0xffffffffu, rQ[mt][rh], 2);
            }
        if (tq == 0) {
#pragma unroll
            for (int mt = 0; mt < 2; mt++)
#pragma unroll
                for (int rh = 0; rh < 2; rh++) {
                    int node = rb*32 + mt*16 + rh*8 + tr;
                    psumS[node*2 + cg] = rS[mt][rh];
                    psumQ[node*2 + cg] = rQ[mt][rh];
                }
        }
        __syncthreads();

        float muv[2][2], rsv[2][2];
#pragma unroll
        for (int mt = 0; mt < 2; mt++)
#pragma unroll
            for (int rh = 0; rh < 2; rh++) {
                int node = rb*32 + mt*16 + rh*8 + tr;
                float S = psumS[node*2] + psumS[node*2+1];
                float Q = psumQ[node*2] + psumQ[node*2+1];
                float mu = S * (1.0f/128.0f);
                muv[mt][rh] = mu;
                rsv[mt][rh] = rsqrtf(Q * (1.0f/128.0f) - mu*mu + 1e-5f);
            }

        if (layer == 0) {
#pragma unroll
            for (int mt = 0; mt < 2; mt++) {
#pragma unroll
                for (int nt = 0; nt < 8; nt++) {
                    int col0 = ob + nt*8 + 2*tq;
                    float2 gg = *reinterpret_cast<const float2*>(&par[128 + col0]);
                    float2 bb = *reinterpret_cast<const float2*>(&par[256 + col0]);
                    int row0 = rb*32 + mt*16 + tr;
                    float v00 = fmaxf((acc[mt][nt][0]-muv[mt][0])*rsv[mt][0]*gg.x + bb.x, 0.f);
                    float v01 = fmaxf((acc[mt][nt][1]-muv[mt][0])*rsv[mt][0]*gg.y + bb.y, 0.f);
                    float v10 = fmaxf((acc[mt][nt][2]-muv[mt][1])*rsv[mt][1]*gg.x + bb.x, 0.f);
                    float v11 = fmaxf((acc[mt][nt][3]-muv[mt][1])*rsv[mt][1]*gg.y + bb.y, 0.f);
                    uint32_t off0 = (uint32_t)row0 * ASTR_B + col0*2;
                    uint32_t off1 = off0 + 8*ASTR_B;
                    *reinterpret_cast<uint32_t*>(smc + AH_B + off0) = pack2(v00, v01);
                    *reinterpret_cast<uint32_t*>(smc + AH_B + off1) = pack2(v10, v11);
                    *reinterpret_cast<uint32_t*>(smc + AL_B + off0) = pack2(v00 - bfr(v00), v01 - bfr(v01));
                    *reinterpret_cast<uint32_t*>(smc + AL_B + off1) = pack2(v10 - bfr(v10), v11 - bfr(v11));
                }
            }
            __syncthreads();
        } else {
            float cm[8][2];
#pragma unroll
            for (int nt = 0; nt < 8; nt++) { cm[nt][0] = -INFINITY; cm[nt][1] = -INFINITY; }
#pragma unroll
            for (int mt = 0; mt < 2; mt++) {
#pragma unroll
                for (int nt = 0; nt < 8; nt++) {
                    int col0 = ob + nt*8 + 2*tq;
                    float2 gg = *reinterpret_cast<const float2*>(&par[128 + col0]);
                    float2 bb = *reinterpret_cast<const float2*>(&par[256 + col0]);
                    float v00 = fmaxf((acc[mt][nt][0]-muv[mt][0])*rsv[mt][0]*gg.x + bb.x, 0.f);
                    float v01 = fmaxf((acc[mt][nt][1]-muv[mt][0])*rsv[mt][0]*gg.y + bb.y, 0.f);
                    float v10 = fmaxf((acc[mt][nt][2]-muv[mt][1])*rsv[mt][1]*gg.x + bb.x, 0.f);
                    float v11 = fmaxf((acc[mt][nt][3]-muv[mt][1])*rsv[mt][1]*gg.y + bb.y, 0.f);
                    cm[nt][0] = fmaxf(cm[nt][0], fmaxf(v00, v10));
                    cm[nt][1] = fmaxf(cm[nt][1], fmaxf(v01, v11));
                }
            }
#pragma unroll
            for (int nt = 0; nt < 8; nt++)
#pragma unroll
                for (int q = 0; q < 2; q++) {
                    cm[nt][q] = fmaxf(cm[nt][q], __shfl_xor_sync(0xffffffffu, cm[nt][q], 4));
                    cm[nt][q] = fmaxf(cm[nt][q], __shfl_xor_sync(0xffffffffu, cm[nt][q], 8));
                    cm[nt][q] = fmaxf(cm[nt][q], __shfl_xor_sync(0xffffffffu, cm[nt][q], 16));
                }
            if (tr == 0) {
#pragma unroll
                for (int nt = 0; nt < 8; nt++) {
                    wmax[w*64 + nt*8 + 2*tq]     = cm[nt][0];
                    wmax[w*64 + nt*8 + 2*tq + 1] = cm[nt][1];
                }
            }
        }
    }
    __syncthreads();

    // ---- final reduce ----
    if (tid < 128) {
        int cgd = tid >> 6, dd = tid & 63;
        float m = -INFINITY;
#pragma unroll
        for (int i = 0; i < 8; i++) m = fmaxf(m, wmax[(cgd*8 + i)*64 + dd]);
        out[(size_t)bm * 256 + cgd*64 + dd]       = m;
        out[(size_t)bm * 256 + 128 + cgd*64 + dd] = m;
    }
}

extern "C" void kernel_launch(void* const* d_in, const int* in_sizes, int n_in,
                              void* d_out, int out_size)
{
    const int INPUT_ELEMS = 8 * 128 * 256 * 8;   // 2,097,152
    const float* inp = nullptr;
    const float* wt[16];
    int wi = 0;
    for (int i = 0; i < n_in; i++) {
        if (in_sizes[i] == INPUT_ELEMS) inp = (const float*)d_in[i];
        else if (wi < 16)               wt[wi++] = (const float*)d_in[i];
    }

    cudaFuncSetAttribute(localgraph_fused_kernel,
                         cudaFuncAttributeMaxDynamicSharedMemorySize, SMEM_BYTES);

    localgraph_fused_kernel<<<8 * 128, NTHREADS, SMEM_BYTES>>>(
        inp,
        wt[0],  wt[1],  wt[2],  wt[3],
        wt[4],  wt[5],  wt[6],  wt[7],
        wt[8],  wt[9],  wt[10], wt[11],
        wt[12], wt[13], wt[14], wt[15],
        (float*)d_out);
}